// round 1
// baseline (speedup 1.0000x reference)
#include <cuda_runtime.h>
#include <math.h>

#define B_  4
#define S_  2048
#define D_  1024
#define H_  16
#define DK_ 64
#define M_  (B_*S_)   // 8192 rows

// ---------------- scratch (static device globals; no runtime allocation) ----
__device__ float g_Q[M_*D_];   // [B,H,S,DK]
__device__ float g_K[M_*D_];   // [B,H,S,DK]
__device__ float g_V[M_*D_];   // [B,H,S,DK]
__device__ float g_AO[M_*D_];  // [B,S,D]

// ---------------------------------------------------------------------------
// NT GEMM:  C[m,n] = sum_k A[m,k] * W[n,k] + bias[n]
// A: [M_, D_] row-major, W: [D_, D_] row-major (nn.Linear weight), both
// K-contiguous -> fully coalesced loads. 128x128 block tile, BK=8, 256
// threads, 8x8 micro-tile per thread, double-buffered smem.
// SCATTER=1: write into [B,H,S,DK] head layout. SCATTER=0: plain [M_,D_].
// ---------------------------------------------------------------------------
template<int SCATTER>
__global__ void __launch_bounds__(256) gemm_nt_bias(
    const float* __restrict__ A, const float* __restrict__ W,
    const float* __restrict__ bias, float* __restrict__ out)
{
    __shared__ float As[2][8][128];
    __shared__ float Bs[2][8][128];

    const int tid  = threadIdx.x;
    const int bm   = blockIdx.y, bn = blockIdx.x;
    const int lrow = tid >> 1;          // 0..127
    const int kp   = (tid & 1) * 4;     // 0 or 4
    const int ty   = tid >> 4, tx = tid & 15;

    const float* aptr = A + (bm*128 + lrow) * D_ + kp;
    const float* wptr = W + (bn*128 + lrow) * D_ + kp;

    float acc[8][8];
#pragma unroll
    for (int i = 0; i < 8; i++)
#pragma unroll
        for (int j = 0; j < 8; j++) acc[i][j] = 0.f;

    // prologue: tile 0
    float4 a = *(const float4*)aptr;
    float4 b = *(const float4*)wptr;
    As[0][kp+0][lrow]=a.x; As[0][kp+1][lrow]=a.y; As[0][kp+2][lrow]=a.z; As[0][kp+3][lrow]=a.w;
    Bs[0][kp+0][lrow]=b.x; Bs[0][kp+1][lrow]=b.y; Bs[0][kp+2][lrow]=b.z; Bs[0][kp+3][lrow]=b.w;
    __syncthreads();

    const int NT = D_ / 8;
    for (int kt = 0; kt < NT; ++kt) {
        const int cur = kt & 1;
        if (kt + 1 < NT) {
            a = *(const float4*)(aptr + (kt+1)*8);
            b = *(const float4*)(wptr + (kt+1)*8);
        }
#pragma unroll
        for (int k = 0; k < 8; k++) {
            float ar[8], br[8];
            float4 t;
            t = *(const float4*)&As[cur][k][ty*4];    ar[0]=t.x; ar[1]=t.y; ar[2]=t.z; ar[3]=t.w;
            t = *(const float4*)&As[cur][k][ty*4+64]; ar[4]=t.x; ar[5]=t.y; ar[6]=t.z; ar[7]=t.w;
            t = *(const float4*)&Bs[cur][k][tx*4];    br[0]=t.x; br[1]=t.y; br[2]=t.z; br[3]=t.w;
            t = *(const float4*)&Bs[cur][k][tx*4+64]; br[4]=t.x; br[5]=t.y; br[6]=t.z; br[7]=t.w;
#pragma unroll
            for (int i = 0; i < 8; i++)
#pragma unroll
                for (int j = 0; j < 8; j++)
                    acc[i][j] = fmaf(ar[i], br[j], acc[i][j]);
        }
        if (kt + 1 < NT) {
            const int nxt = cur ^ 1;
            As[nxt][kp+0][lrow]=a.x; As[nxt][kp+1][lrow]=a.y; As[nxt][kp+2][lrow]=a.z; As[nxt][kp+3][lrow]=a.w;
            Bs[nxt][kp+0][lrow]=b.x; Bs[nxt][kp+1][lrow]=b.y; Bs[nxt][kp+2][lrow]=b.z; Bs[nxt][kp+3][lrow]=b.w;
            __syncthreads();
        }
    }

    // epilogue: bias + (optional) scatter to [B,H,S,DK]
#pragma unroll
    for (int ii = 0; ii < 2; ii++)
#pragma unroll
    for (int i = 0; i < 4; i++) {
        const int m = bm*128 + ty*4 + ii*64 + i;
#pragma unroll
        for (int jj = 0; jj < 2; jj++)
#pragma unroll
        for (int j = 0; j < 4; j++) {
            const int n = bn*128 + tx*4 + jj*64 + j;
            const float v = acc[ii*4+i][jj*4+j] + __ldg(&bias[n]);
            if (SCATTER) {
                const int bb = m >> 11, s = m & (S_-1);
                const int h  = n >> 6,  dk = n & (DK_-1);
                out[(((bb*H_ + h)*S_) + s)*DK_ + dk] = v;
            } else {
                out[m*D_ + n] = v;
            }
        }
    }
}

// ---------------------------------------------------------------------------
// Flash attention, fp32, causal, 64x64 tiles, DK=64.
// Grid: (S/64 query tiles, B*H). 256 threads (16x16), 4x4 micro-tile.
// Q pre-scaled by 1/sqrt(DK). K stored transposed (KT[d][c]) for float4
// reads; P (softmax probs) reuses the KT buffer between phases.
// Output written directly in [B,S,D] layout.
// ---------------------------------------------------------------------------
#define FLASH_SMEM ((64*64 + 2*64*68) * 4)

__global__ void __launch_bounds__(256) flash_attn_kernel(
    const float* __restrict__ Q, const float* __restrict__ K,
    const float* __restrict__ V, float* __restrict__ O)
{
    extern __shared__ float sm[];
    float* Qs = sm;             // 64 x 64
    float* KT = sm + 64*64;     // 64 x 68 : K^T during scores, then P
    float* Vs = KT + 64*68;     // 64 x 68

    const int qi  = blockIdx.x;     // query tile
    const int bh  = blockIdx.y;     // b*H + h
    const int tid = threadIdx.x;
    const int tx  = tid & 15, ty = tid >> 4;
    const int r0  = ty*4, c0 = tx*4;

    // load + pre-scale Q tile
    const float* qg = Q + (bh*S_ + qi*64) * DK_;
#pragma unroll
    for (int f = tid; f < 1024; f += 256) {
        float4 v = ((const float4*)qg)[f];
        v.x *= 0.125f; v.y *= 0.125f; v.z *= 0.125f; v.w *= 0.125f;
        ((float4*)Qs)[f] = v;
    }

    float mrow[4], lrow[4], o[4][4];
#pragma unroll
    for (int i = 0; i < 4; i++) {
        mrow[i] = -INFINITY; lrow[i] = 0.f;
#pragma unroll
        for (int j = 0; j < 4; j++) o[i][j] = 0.f;
    }

    for (int kj = 0; kj <= qi; ++kj) {
        __syncthreads();   // previous iter done reading KT(P)/Vs; also covers Qs on iter 0

        // load K tile transposed: KT[d][c] = K[c][d]
        const float* kg = K + (bh*S_ + kj*64) * DK_;
        for (int f = tid; f < 1024; f += 256) {
            const int c = f >> 4, d4 = (f & 15) << 2;
            float4 v = ((const float4*)kg)[f];
            KT[(d4+0)*68 + c] = v.x;
            KT[(d4+1)*68 + c] = v.y;
            KT[(d4+2)*68 + c] = v.z;
            KT[(d4+3)*68 + c] = v.w;
        }
        // load V tile natural layout (stride 68 keeps float4 alignment)
        const float* vg = V + (bh*S_ + kj*64) * DK_;
        for (int f = tid; f < 1024; f += 256) {
            const int c = f >> 4, d4 = (f & 15) << 2;
            *(float4*)&Vs[c*68 + d4] = ((const float4*)vg)[f];
        }
        __syncthreads();

        // scores: S = Qs @ KT  (4x4 per thread)
        float s[4][4];
#pragma unroll
        for (int i = 0; i < 4; i++)
#pragma unroll
            for (int c = 0; c < 4; c++) s[i][c] = 0.f;

#pragma unroll 4
        for (int d = 0; d < 64; d += 4) {
            float qv[4][4], kv[4][4];
#pragma unroll
            for (int i = 0; i < 4; i++) {
                float4 t = *(const float4*)&Qs[(r0+i)*64 + d];
                qv[i][0]=t.x; qv[i][1]=t.y; qv[i][2]=t.z; qv[i][3]=t.w;
            }
#pragma unroll
            for (int dd = 0; dd < 4; dd++) {
                float4 t = *(const float4*)&KT[(d+dd)*68 + c0];
                kv[dd][0]=t.x; kv[dd][1]=t.y; kv[dd][2]=t.z; kv[dd][3]=t.w;
            }
#pragma unroll
            for (int i = 0; i < 4; i++)
#pragma unroll
                for (int dd = 0; dd < 4; dd++)
#pragma unroll
                    for (int c = 0; c < 4; c++)
                        s[i][c] = fmaf(qv[i][dd], kv[dd][c], s[i][c]);
        }

        // causal mask on the diagonal tile (tile offsets cancel)
        if (kj == qi) {
#pragma unroll
            for (int i = 0; i < 4; i++)
#pragma unroll
                for (int c = 0; c < 4; c++)
                    if (c0 + c > r0 + i) s[i][c] = -1e30f;
        }

        // online softmax (row stats reduced across the 16-lane tx group)
        float p[4][4];
#pragma unroll
        for (int i = 0; i < 4; i++) {
            float mt = fmaxf(fmaxf(s[i][0], s[i][1]), fmaxf(s[i][2], s[i][3]));
#pragma unroll
            for (int off = 8; off >= 1; off >>= 1)
                mt = fmaxf(mt, __shfl_xor_sync(0xffffffffu, mt, off));
            const float mn   = fmaxf(mrow[i], mt);
            const float corr = __expf(mrow[i] - mn);
            float ls = 0.f;
#pragma unroll
            for (int c = 0; c < 4; c++) { p[i][c] = __expf(s[i][c] - mn); ls += p[i][c]; }
#pragma unroll
            for (int off = 8; off >= 1; off >>= 1)
                ls += __shfl_xor_sync(0xffffffffu, ls, off);
            lrow[i] = lrow[i]*corr + ls;
            mrow[i] = mn;
#pragma unroll
            for (int c = 0; c < 4; c++) o[i][c] *= corr;
        }

        __syncthreads();             // everyone finished reading KT as K^T
        // write P into the KT buffer: P[r][k]
#pragma unroll
        for (int i = 0; i < 4; i++)
            *(float4*)&KT[(r0+i)*68 + c0] = make_float4(p[i][0], p[i][1], p[i][2], p[i][3]);
        __syncthreads();

        // O += P @ V
#pragma unroll 4
        for (int k = 0; k < 64; k += 4) {
            float pv[4][4], vv[4][4];
#pragma unroll
            for (int i = 0; i < 4; i++) {
                float4 t = *(const float4*)&KT[(r0+i)*68 + k];
                pv[i][0]=t.x; pv[i][1]=t.y; pv[i][2]=t.z; pv[i][3]=t.w;
            }
#pragma unroll
            for (int kk = 0; kk < 4; kk++) {
                float4 t = *(const float4*)&Vs[(k+kk)*68 + c0];
                vv[kk][0]=t.x; vv[kk][1]=t.y; vv[kk][2]=t.z; vv[kk][3]=t.w;
            }
#pragma unroll
            for (int i = 0; i < 4; i++)
#pragma unroll
                for (int kk = 0; kk < 4; kk++)
#pragma unroll
                    for (int c = 0; c < 4; c++)
                        o[i][c] = fmaf(pv[i][kk], vv[kk][c], o[i][c]);
        }
    }

    // finalize: divide by l, write directly in [B,S,D] layout
    const int bb = bh >> 4, h = bh & 15;
#pragma unroll
    for (int i = 0; i < 4; i++) {
        const float inv  = 1.0f / lrow[i];
        const int   srow = qi*64 + r0 + i;
        float* og = O + ((bb*S_ + srow)*D_) + h*DK_ + c0;
        *(float4*)og = make_float4(o[i][0]*inv, o[i][1]*inv, o[i][2]*inv, o[i][3]*inv);
    }
}

// ---------------------------------------------------------------------------
// launch: QKV projections (scatter to heads) -> flash attention -> out proj
// d_in order: q, k, v, mask(ignored: known causal tril), w_q,b_q, w_k,b_k,
//             w_v,b_v, w_o,b_o
// ---------------------------------------------------------------------------
extern "C" void kernel_launch(void* const* d_in, const int* in_sizes, int n_in,
                              void* d_out, int out_size)
{
    const float* q   = (const float*)d_in[0];
    const float* k   = (const float*)d_in[1];
    const float* v   = (const float*)d_in[2];
    const float* w_q = (const float*)d_in[4];
    const float* b_q = (const float*)d_in[5];
    const float* w_k = (const float*)d_in[6];
    const float* b_k = (const float*)d_in[7];
    const float* w_v = (const float*)d_in[8];
    const float* b_v = (const float*)d_in[9];
    const float* w_o = (const float*)d_in[10];
    const float* b_o = (const float*)d_in[11];
    float* out = (float*)d_out;

    float *Qp, *Kp, *Vp, *AOp;
    cudaGetSymbolAddress((void**)&Qp,  g_Q);
    cudaGetSymbolAddress((void**)&Kp,  g_K);
    cudaGetSymbolAddress((void**)&Vp,  g_V);
    cudaGetSymbolAddress((void**)&AOp, g_AO);

    dim3 ggrid(D_/128, M_/128);
    gemm_nt_bias<1><<<ggrid, 256>>>(q, w_q, b_q, Qp);
    gemm_nt_bias<1><<<ggrid, 256>>>(k, w_k, b_k, Kp);
    gemm_nt_bias<1><<<ggrid, 256>>>(v, w_v, b_v, Vp);

    cudaFuncSetAttribute(flash_attn_kernel,
                         cudaFuncAttributeMaxDynamicSharedMemorySize, FLASH_SMEM);
    flash_attn_kernel<<<dim3(S_/64, B_*H_), 256, FLASH_SMEM>>>(Qp, Kp, Vp, AOp);

    gemm_nt_bias<0><<<ggrid, 256>>>(AOp, w_o, b_o, out);
}

// round 6
// speedup vs baseline: 1.1102x; 1.1102x over previous
#include <cuda_runtime.h>
#include <cstdint>
#include <math.h>

#define B_  4
#define S_  2048
#define D_  1024
#define H_  16
#define DK_ 64
#define M_  (B_*S_)   // 8192 rows

// ---------------- scratch (static device globals; no runtime allocation) ----
__device__ float g_Q[M_*D_];   // [B,H,S,DK]
__device__ float g_K[M_*D_];   // [B,H,S,DK]
__device__ float g_V[M_*D_];   // [B,H,S,DK]
__device__ float g_AO[M_*D_];  // [B,S,D]

// ---------------------------------------------------------------------------
// Round-1 proven FFMA NT GEMM (used for Q/K/V projections).
// ---------------------------------------------------------------------------
template<int SCATTER>
__global__ void __launch_bounds__(256) gemm_nt_bias(
    const float* __restrict__ A, const float* __restrict__ W,
    const float* __restrict__ bias, float* __restrict__ out)
{
    __shared__ float As[2][8][128];
    __shared__ float Bs[2][8][128];

    const int tid  = threadIdx.x;
    const int bm   = blockIdx.y, bn = blockIdx.x;
    const int lrow = tid >> 1;
    const int kp   = (tid & 1) * 4;
    const int ty   = tid >> 4, tx = tid & 15;

    const float* aptr = A + (bm*128 + lrow) * D_ + kp;
    const float* wptr = W + (bn*128 + lrow) * D_ + kp;

    float acc[8][8];
#pragma unroll
    for (int i = 0; i < 8; i++)
#pragma unroll
        for (int j = 0; j < 8; j++) acc[i][j] = 0.f;

    float4 a = *(const float4*)aptr;
    float4 b = *(const float4*)wptr;
    As[0][kp+0][lrow]=a.x; As[0][kp+1][lrow]=a.y; As[0][kp+2][lrow]=a.z; As[0][kp+3][lrow]=a.w;
    Bs[0][kp+0][lrow]=b.x; Bs[0][kp+1][lrow]=b.y; Bs[0][kp+2][lrow]=b.z; Bs[0][kp+3][lrow]=b.w;
    __syncthreads();

    const int NT = D_ / 8;
    for (int kt = 0; kt < NT; ++kt) {
        const int cur = kt & 1;
        if (kt + 1 < NT) {
            a = *(const float4*)(aptr + (kt+1)*8);
            b = *(const float4*)(wptr + (kt+1)*8);
        }
#pragma unroll
        for (int k = 0; k < 8; k++) {
            float ar[8], br[8];
            float4 t;
            t = *(const float4*)&As[cur][k][ty*4];    ar[0]=t.x; ar[1]=t.y; ar[2]=t.z; ar[3]=t.w;
            t = *(const float4*)&As[cur][k][ty*4+64]; ar[4]=t.x; ar[5]=t.y; ar[6]=t.z; ar[7]=t.w;
            t = *(const float4*)&Bs[cur][k][tx*4];    br[0]=t.x; br[1]=t.y; br[2]=t.z; br[3]=t.w;
            t = *(const float4*)&Bs[cur][k][tx*4+64]; br[4]=t.x; br[5]=t.y; br[6]=t.z; br[7]=t.w;
#pragma unroll
            for (int i = 0; i < 8; i++)
#pragma unroll
                for (int j = 0; j < 8; j++)
                    acc[i][j] = fmaf(ar[i], br[j], acc[i][j]);
        }
        if (kt + 1 < NT) {
            const int nxt = cur ^ 1;
            As[nxt][kp+0][lrow]=a.x; As[nxt][kp+1][lrow]=a.y; As[nxt][kp+2][lrow]=a.z; As[nxt][kp+3][lrow]=a.w;
            Bs[nxt][kp+0][lrow]=b.x; Bs[nxt][kp+1][lrow]=b.y; Bs[nxt][kp+2][lrow]=b.z; Bs[nxt][kp+3][lrow]=b.w;
            __syncthreads();
        }
    }

#pragma unroll
    for (int ii = 0; ii < 2; ii++)
#pragma unroll
    for (int i = 0; i < 4; i++) {
        const int m = bm*128 + ty*4 + ii*64 + i;
#pragma unroll
        for (int jj = 0; jj < 2; jj++)
#pragma unroll
        for (int j = 0; j < 4; j++) {
            const int n = bn*128 + tx*4 + jj*64 + j;
            const float v = acc[ii*4+i][jj*4+j] + __ldg(&bias[n]);
            if (SCATTER) {
                const int bb = m >> 11, s = m & (S_-1);
                const int h  = n >> 6,  dk = n & (DK_-1);
                out[(((bb*H_ + h)*S_) + s)*DK_ + dk] = v;
            } else {
                out[m*D_ + n] = v;
            }
        }
    }
}

// ---------------- mma.sync helpers (compute_100-safe PTX, sm_80+) ----------
__device__ __forceinline__ uint32_t f2tf32(float f) {
    uint32_t o;
    asm("cvt.rna.tf32.f32 %0, %1;" : "=r"(o) : "f"(f));
    return o;
}
__device__ __forceinline__ void mma_tf32(float c[4], const uint32_t a[4],
                                         uint32_t b0, uint32_t b1) {
    asm volatile(
        "mma.sync.aligned.m16n8k8.row.col.f32.tf32.tf32.f32 "
        "{%0,%1,%2,%3}, {%4,%5,%6,%7}, {%8,%9}, {%0,%1,%2,%3};"
        : "+f"(c[0]), "+f"(c[1]), "+f"(c[2]), "+f"(c[3])
        : "r"(a[0]), "r"(a[1]), "r"(a[2]), "r"(a[3]), "r"(b0), "r"(b1));
}

// ---------------------------------------------------------------------------
// tf32 mma.sync NT GEMM (BISECT: used ONLY for the output projection).
// CTA tile 128x128, BK=32, 8 warps (4M x 2N), warp tile 32x64.
// ---------------------------------------------------------------------------
#define BK_    32
#define KSTR   36
#define TBUF   (128*KSTR)
#define SMEM_GEMM (4*TBUF*4)              // 73728 B

__device__ __forceinline__ void stage_tile(
    const float* __restrict__ src, float* __restrict__ dst, int kt, int tid)
{
#pragma unroll
    for (int u = 0; u < 4; u++) {
        const int f = tid + u*256;
        const int r = f >> 3, q = f & 7;
        float4 v = *(const float4*)(src + (size_t)r*D_ + kt*BK_ + q*4);
        uint32_t* d = (uint32_t*)(dst + r*KSTR + q*4);
        d[0] = f2tf32(v.x); d[1] = f2tf32(v.y);
        d[2] = f2tf32(v.z); d[3] = f2tf32(v.w);
    }
}

__global__ void __launch_bounds__(256, 2) gemm_mma_out(
    const float* __restrict__ A, const float* __restrict__ W,
    const float* __restrict__ bias, float* __restrict__ out)
{
    extern __shared__ float sm[];   // [A0][B0][A1][B1]
    const int tid  = threadIdx.x;
    const int wid  = tid >> 5, lane = tid & 31;
    const int g    = lane >> 2, t4 = lane & 3;
    const int warpM = wid >> 1, warpN = wid & 1;
    const int bm = blockIdx.y, bn = blockIdx.x;

    float c[2][8][4];
#pragma unroll
    for (int i = 0; i < 2; i++)
#pragma unroll
        for (int j = 0; j < 8; j++)
#pragma unroll
            for (int r = 0; r < 4; r++) c[i][j][r] = 0.f;

    const float* Abase = A + (size_t)(bm*128)*D_;
    const float* Wbase = W + (size_t)(bn*128)*D_;

    stage_tile(Abase, sm + 0*TBUF, 0, tid);
    stage_tile(Wbase, sm + 1*TBUF, 0, tid);
    __syncthreads();

    const int NT = D_ / BK_;
    for (int kt = 0; kt < NT; ++kt) {
        const int cur = kt & 1;
        if (kt + 1 < NT) {
            const int nxt = cur ^ 1;
            stage_tile(Abase, sm + (2*nxt + 0)*TBUF, kt + 1, tid);
            stage_tile(Wbase, sm + (2*nxt + 1)*TBUF, kt + 1, tid);
        }

        const uint32_t* As = (const uint32_t*)(sm + (2*cur + 0)*TBUF);
        const uint32_t* Bs = (const uint32_t*)(sm + (2*cur + 1)*TBUF);
#pragma unroll
        for (int ks = 0; ks < 4; ++ks) {
            const int k0 = ks*8 + t4;
            uint32_t a[2][4];
#pragma unroll
            for (int i = 0; i < 2; i++) {
                const int mb = warpM*32 + i*16;
                a[i][0] = As[(mb + g    )*KSTR + k0    ];
                a[i][1] = As[(mb + 8 + g)*KSTR + k0    ];
                a[i][2] = As[(mb + g    )*KSTR + k0 + 4];
                a[i][3] = As[(mb + 8 + g)*KSTR + k0 + 4];
            }
#pragma unroll
            for (int j = 0; j < 8; j++) {
                const int nb = warpN*64 + j*8;
                const uint32_t b0 = Bs[(nb + g)*KSTR + k0    ];
                const uint32_t b1 = Bs[(nb + g)*KSTR + k0 + 4];
                mma_tf32(c[0][j], a[0], b0, b1);
                mma_tf32(c[1][j], a[1], b0, b1);
            }
        }
        __syncthreads();
    }

#pragma unroll
    for (int i = 0; i < 2; i++) {
        const int mrow = bm*128 + warpM*32 + i*16 + g;
#pragma unroll
        for (int j = 0; j < 8; j++) {
            const int n = bn*128 + warpN*64 + j*8 + 2*t4;
            const float bx = __ldg(&bias[n]), by = __ldg(&bias[n+1]);
#pragma unroll
            for (int rr = 0; rr < 2; rr++) {
                const int m = mrow + rr*8;
                float2 v = make_float2(c[i][j][2*rr] + bx, c[i][j][2*rr+1] + by);
                *(float2*)&out[(size_t)m*D_ + n] = v;
            }
        }
    }
}

// ---------------------------------------------------------------------------
// Flash attention (round-1 proven): fp32 FFMA, causal, 64x64 tiles.
// ---------------------------------------------------------------------------
#define FLASH_SMEM ((64*64 + 2*64*68) * 4)

__global__ void __launch_bounds__(256) flash_attn_kernel(
    const float* __restrict__ Q, const float* __restrict__ K,
    const float* __restrict__ V, float* __restrict__ O)
{
    extern __shared__ float smf[];
    float* Qs = smf;
    float* KT = smf + 64*64;
    float* Vs = KT + 64*68;

    const int qi  = blockIdx.x;
    const int bh  = blockIdx.y;
    const int tid = threadIdx.x;
    const int tx  = tid & 15, ty = tid >> 4;
    const int r0  = ty*4, c0 = tx*4;

    const float* qg = Q + (bh*S_ + qi*64) * DK_;
#pragma unroll
    for (int f = tid; f < 1024; f += 256) {
        float4 v = ((const float4*)qg)[f];
        v.x *= 0.125f; v.y *= 0.125f; v.z *= 0.125f; v.w *= 0.125f;
        ((float4*)Qs)[f] = v;
    }

    float mrow[4], lrow[4], o[4][4];
#pragma unroll
    for (int i = 0; i < 4; i++) {
        mrow[i] = -INFINITY; lrow[i] = 0.f;
#pragma unroll
        for (int j = 0; j < 4; j++) o[i][j] = 0.f;
    }

    for (int kj = 0; kj <= qi; ++kj) {
        __syncthreads();

        const float* kg = K + (bh*S_ + kj*64) * DK_;
        for (int f = tid; f < 1024; f += 256) {
            const int c = f >> 4, d4 = (f & 15) << 2;
            float4 v = ((const float4*)kg)[f];
            KT[(d4+0)*68 + c] = v.x;
            KT[(d4+1)*68 + c] = v.y;
            KT[(d4+2)*68 + c] = v.z;
            KT[(d4+3)*68 + c] = v.w;
        }
        const float* vg = V + (bh*S_ + kj*64) * DK_;
        for (int f = tid; f < 1024; f += 256) {
            const int c = f >> 4, d4 = (f & 15) << 2;
            *(float4*)&Vs[c*68 + d4] = ((const float4*)vg)[f];
        }
        __syncthreads();

        float s[4][4];
#pragma unroll
        for (int i = 0; i < 4; i++)
#pragma unroll
            for (int c = 0; c < 4; c++) s[i][c] = 0.f;

#pragma unroll 4
        for (int d = 0; d < 64; d += 4) {
            float qv[4][4], kv[4][4];
#pragma unroll
            for (int i = 0; i < 4; i++) {
                float4 t = *(const float4*)&Qs[(r0+i)*64 + d];
                qv[i][0]=t.x; qv[i][1]=t.y; qv[i][2]=t.z; qv[i][3]=t.w;
            }
#pragma unroll
            for (int dd = 0; dd < 4; dd++) {
                float4 t = *(const float4*)&KT[(d+dd)*68 + c0];
                kv[dd][0]=t.x; kv[dd][1]=t.y; kv[dd][2]=t.z; kv[dd][3]=t.w;
            }
#pragma unroll
            for (int i = 0; i < 4; i++)
#pragma unroll
                for (int dd = 0; dd < 4; dd++)
#pragma unroll
                    for (int c = 0; c < 4; c++)
                        s[i][c] = fmaf(qv[i][dd], kv[dd][c], s[i][c]);
        }

        if (kj == qi) {
#pragma unroll
            for (int i = 0; i < 4; i++)
#pragma unroll
                for (int c = 0; c < 4; c++)
                    if (c0 + c > r0 + i) s[i][c] = -1e30f;
        }

        float p[4][4];
#pragma unroll
        for (int i = 0; i < 4; i++) {
            float mt = fmaxf(fmaxf(s[i][0], s[i][1]), fmaxf(s[i][2], s[i][3]));
#pragma unroll
            for (int off = 8; off >= 1; off >>= 1)
                mt = fmaxf(mt, __shfl_xor_sync(0xffffffffu, mt, off));
            const float mn   = fmaxf(mrow[i], mt);
            const float corr = __expf(mrow[i] - mn);
            float ls = 0.f;
#pragma unroll
            for (int c = 0; c < 4; c++) { p[i][c] = __expf(s[i][c] - mn); ls += p[i][c]; }
#pragma unroll
            for (int off = 8; off >= 1; off >>= 1)
                ls += __shfl_xor_sync(0xffffffffu, ls, off);
            lrow[i] = lrow[i]*corr + ls;
            mrow[i] = mn;
#pragma unroll
            for (int c = 0; c < 4; c++) o[i][c] *= corr;
        }

        __syncthreads();
#pragma unroll
        for (int i = 0; i < 4; i++)
            *(float4*)&KT[(r0+i)*68 + c0] = make_float4(p[i][0], p[i][1], p[i][2], p[i][3]);
        __syncthreads();

#pragma unroll 4
        for (int k = 0; k < 64; k += 4) {
            float pv[4][4], vv[4][4];
#pragma unroll
            for (int i = 0; i < 4; i++) {
                float4 t = *(const float4*)&KT[(r0+i)*68 + k];
                pv[i][0]=t.x; pv[i][1]=t.y; pv[i][2]=t.z; pv[i][3]=t.w;
            }
#pragma unroll
            for (int kk = 0; kk < 4; kk++) {
                float4 t = *(const float4*)&Vs[(k+kk)*68 + c0];
                vv[kk][0]=t.x; vv[kk][1]=t.y; vv[kk][2]=t.z; vv[kk][3]=t.w;
            }
#pragma unroll
            for (int i = 0; i < 4; i++)
#pragma unroll
                for (int kk = 0; kk < 4; kk++)
#pragma unroll
                    for (int c = 0; c < 4; c++)
                        o[i][c] = fmaf(pv[i][kk], vv[kk][c], o[i][c]);
        }
    }

    const int bb = bh >> 4, h = bh & 15;
#pragma unroll
    for (int i = 0; i < 4; i++) {
        const float inv  = 1.0f / lrow[i];
        const int   srow = qi*64 + r0 + i;
        float* og = O + ((bb*S_ + srow)*D_) + h*DK_ + c0;
        *(float4*)og = make_float4(o[i][0]*inv, o[i][1]*inv, o[i][2]*inv, o[i][3]*inv);
    }
}

// ---------------------------------------------------------------------------
extern "C" void kernel_launch(void* const* d_in, const int* in_sizes, int n_in,
                              void* d_out, int out_size)
{
    const float* q   = (const float*)d_in[0];
    const float* k   = (const float*)d_in[1];
    const float* v   = (const float*)d_in[2];
    const float* w_q = (const float*)d_in[4];
    const float* b_q = (const float*)d_in[5];
    const float* w_k = (const float*)d_in[6];
    const float* b_k = (const float*)d_in[7];
    const float* w_v = (const float*)d_in[8];
    const float* b_v = (const float*)d_in[9];
    const float* w_o = (const float*)d_in[10];
    const float* b_o = (const float*)d_in[11];
    float* out = (float*)d_out;

    float *Qp, *Kp, *Vp, *AOp;
    cudaGetSymbolAddress((void**)&Qp,  g_Q);
    cudaGetSymbolAddress((void**)&Kp,  g_K);
    cudaGetSymbolAddress((void**)&Vp,  g_V);
    cudaGetSymbolAddress((void**)&AOp, g_AO);

    cudaFuncSetAttribute(gemm_mma_out, cudaFuncAttributeMaxDynamicSharedMemorySize, SMEM_GEMM);
    cudaFuncSetAttribute(flash_attn_kernel, cudaFuncAttributeMaxDynamicSharedMemorySize, FLASH_SMEM);

    dim3 ggrid(D_/128, M_/128);   // 8 x 64
    gemm_nt_bias<1><<<ggrid, 256>>>(q, w_q, b_q, Qp);
    gemm_nt_bias<1><<<ggrid, 256>>>(k, w_k, b_k, Kp);
    gemm_nt_bias<1><<<ggrid, 256>>>(v, w_v, b_v, Vp);

    flash_attn_kernel<<<dim3(S_/64, B_*H_), 256, FLASH_SMEM>>>(Qp, Kp, Vp, AOp);

    gemm_mma_out<<<ggrid, 256, SMEM_GEMM>>>(AOp, w_o, b_o, out);
}

// round 7
// speedup vs baseline: 2.6703x; 2.4053x over previous
#include <cuda_runtime.h>
#include <cstdint>
#include <math.h>

#define B_  4
#define S_  2048
#define D_  1024
#define H_  16
#define DK_ 64
#define M_  (B_*S_)   // 8192

// ---------------- scratch ---------------------------------------------------
__device__ float g_Q[M_*D_];   // [B,H,S,DK]
__device__ float g_K[M_*D_];   // [B,H,S,DK]
__device__ float g_V[M_*D_];   // [B,H,S,DK]
__device__ float g_AO[M_*D_];  // [B,S,D]

// ---------------- mma.sync helpers (compute_100-safe PTX, sm_80+) ----------
__device__ __forceinline__ uint32_t f2tf32(float f) {
    uint32_t o;
    asm("cvt.rna.tf32.f32 %0, %1;" : "=r"(o) : "f"(f));
    return o;
}
__device__ __forceinline__ void mma_tf32(float c[4], const uint32_t a[4],
                                         uint32_t b0, uint32_t b1) {
    asm volatile(
        "mma.sync.aligned.m16n8k8.row.col.f32.tf32.tf32.f32 "
        "{%0,%1,%2,%3}, {%4,%5,%6,%7}, {%8,%9}, {%0,%1,%2,%3};"
        : "+f"(c[0]), "+f"(c[1]), "+f"(c[2]), "+f"(c[3])
        : "r"(a[0]), "r"(a[1]), "r"(a[2]), "r"(a[3]), "r"(b0), "r"(b1));
}

// ---------------------------------------------------------------------------
// tf32 mma.sync NT GEMM (proven round-6): C = A@W^T + bias
// CTA 128x128, BK=32, 8 warps (4Mx2N), warp tile 32x64, double-buffered.
// ---------------------------------------------------------------------------
#define BK_    32
#define KSTR   36
#define TBUF   (128*KSTR)
#define SMEM_GEMM (4*TBUF*4)              // 73728 B

__device__ __forceinline__ void stage_tile(
    const float* __restrict__ src, float* __restrict__ dst, int kt, int tid)
{
#pragma unroll
    for (int u = 0; u < 4; u++) {
        const int f = tid + u*256;
        const int r = f >> 3, q = f & 7;
        float4 v = *(const float4*)(src + (size_t)r*D_ + kt*BK_ + q*4);
        uint32_t* d = (uint32_t*)(dst + r*KSTR + q*4);
        d[0] = f2tf32(v.x); d[1] = f2tf32(v.y);
        d[2] = f2tf32(v.z); d[3] = f2tf32(v.w);
    }
}

template<int SCATTER>
__global__ void __launch_bounds__(256, 2) gemm_mma(
    const float* __restrict__ A, const float* __restrict__ W,
    const float* __restrict__ bias, float* __restrict__ out)
{
    extern __shared__ float sm[];   // [A0][B0][A1][B1]
    const int tid  = threadIdx.x;
    const int wid  = tid >> 5, lane = tid & 31;
    const int g    = lane >> 2, t4 = lane & 3;
    const int warpM = wid >> 1, warpN = wid & 1;
    const int bm = blockIdx.y, bn = blockIdx.x;

    float c[2][8][4];
#pragma unroll
    for (int i = 0; i < 2; i++)
#pragma unroll
        for (int j = 0; j < 8; j++)
#pragma unroll
            for (int r = 0; r < 4; r++) c[i][j][r] = 0.f;

    const float* Abase = A + (size_t)(bm*128)*D_;
    const float* Wbase = W + (size_t)(bn*128)*D_;

    stage_tile(Abase, sm + 0*TBUF, 0, tid);
    stage_tile(Wbase, sm + 1*TBUF, 0, tid);
    __syncthreads();

    const int NT = D_ / BK_;
    for (int kt = 0; kt < NT; ++kt) {
        const int cur = kt & 1;
        if (kt + 1 < NT) {
            const int nxt = cur ^ 1;
            stage_tile(Abase, sm + (2*nxt + 0)*TBUF, kt + 1, tid);
            stage_tile(Wbase, sm + (2*nxt + 1)*TBUF, kt + 1, tid);
        }

        const uint32_t* As = (const uint32_t*)(sm + (2*cur + 0)*TBUF);
        const uint32_t* Bs = (const uint32_t*)(sm + (2*cur + 1)*TBUF);
#pragma unroll
        for (int ks = 0; ks < 4; ++ks) {
            const int k0 = ks*8 + t4;
            uint32_t a[2][4];
#pragma unroll
            for (int i = 0; i < 2; i++) {
                const int mb = warpM*32 + i*16;
                a[i][0] = As[(mb + g    )*KSTR + k0    ];
                a[i][1] = As[(mb + 8 + g)*KSTR + k0    ];
                a[i][2] = As[(mb + g    )*KSTR + k0 + 4];
                a[i][3] = As[(mb + 8 + g)*KSTR + k0 + 4];
            }
#pragma unroll
            for (int j = 0; j < 8; j++) {
                const int nb = warpN*64 + j*8;
                const uint32_t b0 = Bs[(nb + g)*KSTR + k0    ];
                const uint32_t b1 = Bs[(nb + g)*KSTR + k0 + 4];
                mma_tf32(c[0][j], a[0], b0, b1);
                mma_tf32(c[1][j], a[1], b0, b1);
            }
        }
        __syncthreads();
    }

#pragma unroll
    for (int i = 0; i < 2; i++) {
        const int mrow = bm*128 + warpM*32 + i*16 + g;
#pragma unroll
        for (int j = 0; j < 8; j++) {
            const int n = bn*128 + warpN*64 + j*8 + 2*t4;
            const float bx = __ldg(&bias[n]), by = __ldg(&bias[n+1]);
#pragma unroll
            for (int rr = 0; rr < 2; rr++) {
                const int m = mrow + rr*8;
                float2 v = make_float2(c[i][j][2*rr] + bx, c[i][j][2*rr+1] + by);
                if (SCATTER) {
                    const int bb = m >> 11, s = m & (S_-1);
                    const int h  = n >> 6,  dk = n & (DK_-1);
                    *(float2*)&out[((size_t)(bb*H_ + h)*S_ + s)*DK_ + dk] = v;
                } else {
                    *(float2*)&out[(size_t)m*D_ + n] = v;
                }
            }
        }
    }
}

// ---------------------------------------------------------------------------
// Flash attention on tensor cores (tf32 mma.sync), causal, 64x64 tiles.
// 128 threads = 4 warps; warp w owns query rows [w*16, w*16+16).
// K and V tiles stored NATURAL (key-major) — B-fragment indexing handles
// both (n,k) for QK^T and (k,n) for PV without any transpose.
// P relayout C-frag -> A-frag via SMEM (warp-local rows, __syncwarp only).
// ---------------------------------------------------------------------------
#define FP_   68                            // padded row stride (words)
#define FLASH_SMEM (4*64*FP_*4)             // Qs,Ks,Vs,Ps = 69632 B

__global__ void __launch_bounds__(128) flash_mma(
    const float* __restrict__ Q, const float* __restrict__ K,
    const float* __restrict__ V, float* __restrict__ O)
{
    extern __shared__ uint32_t su[];
    uint32_t* Qs = su;                 // [64][FP_] tf32, value Q[q][d]
    uint32_t* Ks = Qs + 64*FP_;        // [64][FP_] tf32, value K[k'][d]
    uint32_t* Vs = Ks + 64*FP_;        // [64][FP_] tf32, value V[k'][d]
    uint32_t* Ps = Vs + 64*FP_;        // [64][FP_] tf32, value P[q][k']

    const int qi  = blockIdx.x, bh = blockIdx.y;
    const int tid = threadIdx.x, wid = tid >> 5, lane = tid & 31;
    const int g   = lane >> 2, t4 = lane & 3;
    const int r0  = wid*16;

    // load Q tile, pre-scale by 1/sqrt(DK)=0.125, convert tf32
    const float* qg = Q + (size_t)(bh*S_ + qi*64) * DK_;
#pragma unroll
    for (int f = tid; f < 1024; f += 128) {
        const int r = f >> 4, c4 = (f & 15) << 2;
        float4 v = ((const float4*)qg)[f];
        Qs[r*FP_ + c4 + 0] = f2tf32(v.x*0.125f);
        Qs[r*FP_ + c4 + 1] = f2tf32(v.y*0.125f);
        Qs[r*FP_ + c4 + 2] = f2tf32(v.z*0.125f);
        Qs[r*FP_ + c4 + 3] = f2tf32(v.w*0.125f);
    }

    float co[8][4];
#pragma unroll
    for (int j = 0; j < 8; j++)
#pragma unroll
        for (int r = 0; r < 4; r++) co[j][r] = 0.f;
    float mrow[2] = {-INFINITY, -INFINITY};
    float lrow[2] = {0.f, 0.f};

    for (int kj = 0; kj <= qi; ++kj) {
        __syncthreads();   // all warps done with Ks/Vs of prev iter (covers Qs on iter 0)

        const float* kg = K + (size_t)(bh*S_ + kj*64) * DK_;
        const float* vg = V + (size_t)(bh*S_ + kj*64) * DK_;
#pragma unroll
        for (int f = tid; f < 1024; f += 128) {
            const int r = f >> 4, c4 = (f & 15) << 2;
            float4 kv = ((const float4*)kg)[f];
            Ks[r*FP_ + c4 + 0] = f2tf32(kv.x);
            Ks[r*FP_ + c4 + 1] = f2tf32(kv.y);
            Ks[r*FP_ + c4 + 2] = f2tf32(kv.z);
            Ks[r*FP_ + c4 + 3] = f2tf32(kv.w);
            float4 vv = ((const float4*)vg)[f];
            Vs[r*FP_ + c4 + 0] = f2tf32(vv.x);
            Vs[r*FP_ + c4 + 1] = f2tf32(vv.y);
            Vs[r*FP_ + c4 + 2] = f2tf32(vv.z);
            Vs[r*FP_ + c4 + 3] = f2tf32(vv.w);
        }
        __syncthreads();

        // ---- S = Q @ K^T : A = Qs rows r0..r0+15, B value (n=k', k=d) = Ks[k'][d]
        float cs[8][4];
#pragma unroll
        for (int j = 0; j < 8; j++)
#pragma unroll
            for (int r = 0; r < 4; r++) cs[j][r] = 0.f;
#pragma unroll
        for (int ks = 0; ks < 8; ++ks) {
            const int k0 = ks*8 + t4;
            uint32_t a[4];
            a[0] = Qs[(r0 + g    )*FP_ + k0    ];
            a[1] = Qs[(r0 + 8 + g)*FP_ + k0    ];
            a[2] = Qs[(r0 + g    )*FP_ + k0 + 4];
            a[3] = Qs[(r0 + 8 + g)*FP_ + k0 + 4];
#pragma unroll
            for (int j = 0; j < 8; j++) {
                const uint32_t b0 = Ks[(j*8 + g)*FP_ + k0    ];
                const uint32_t b1 = Ks[(j*8 + g)*FP_ + k0 + 4];
                mma_tf32(cs[j], a, b0, b1);
            }
        }

        // ---- causal mask on diagonal tile (tile-local rows/cols)
        if (kj == qi) {
#pragma unroll
            for (int j = 0; j < 8; j++)
#pragma unroll
                for (int rr = 0; rr < 2; rr++)
#pragma unroll
                    for (int e = 0; e < 2; e++) {
                        const int row = r0 + g + 8*rr;
                        const int col = j*8 + 2*t4 + e;
                        if (col > row) cs[j][2*rr + e] = -1e30f;
                    }
        }

        // ---- online softmax (row stats over quad: lanes sharing g)
#pragma unroll
        for (int rr = 0; rr < 2; rr++) {
            float mt = -INFINITY;
#pragma unroll
            for (int j = 0; j < 8; j++)
                mt = fmaxf(mt, fmaxf(cs[j][2*rr], cs[j][2*rr + 1]));
            mt = fmaxf(mt, __shfl_xor_sync(0xffffffffu, mt, 1));
            mt = fmaxf(mt, __shfl_xor_sync(0xffffffffu, mt, 2));
            const float mn   = fmaxf(mrow[rr], mt);
            const float corr = __expf(mrow[rr] - mn);
            float ls = 0.f;
#pragma unroll
            for (int j = 0; j < 8; j++) {
                const float p0 = __expf(cs[j][2*rr    ] - mn);
                const float p1 = __expf(cs[j][2*rr + 1] - mn);
                cs[j][2*rr] = p0; cs[j][2*rr + 1] = p1;
                ls += p0 + p1;
            }
            ls += __shfl_xor_sync(0xffffffffu, ls, 1);
            ls += __shfl_xor_sync(0xffffffffu, ls, 2);
            lrow[rr] = lrow[rr]*corr + ls;
            mrow[rr] = mn;
#pragma unroll
            for (int j = 0; j < 8; j++) {
                co[j][2*rr] *= corr; co[j][2*rr + 1] *= corr;
            }
        }

        // ---- P -> SMEM (tf32), warp-local rows only
#pragma unroll
        for (int rr = 0; rr < 2; rr++) {
            const int row = r0 + g + 8*rr;
#pragma unroll
            for (int j = 0; j < 8; j++) {
                const int idx = row*FP_ + j*8 + 2*t4;
                Ps[idx    ] = f2tf32(cs[j][2*rr    ]);
                Ps[idx + 1] = f2tf32(cs[j][2*rr + 1]);
            }
        }
        __syncwarp();

        // ---- O += P @ V : A = Ps rows, B value (k=k', n=d) = Vs[k'][d]
#pragma unroll
        for (int ks = 0; ks < 8; ++ks) {
            const int k0 = ks*8 + t4;
            uint32_t a[4];
            a[0] = Ps[(r0 + g    )*FP_ + k0    ];
            a[1] = Ps[(r0 + 8 + g)*FP_ + k0    ];
            a[2] = Ps[(r0 + g    )*FP_ + k0 + 4];
            a[3] = Ps[(r0 + 8 + g)*FP_ + k0 + 4];
#pragma unroll
            for (int j = 0; j < 8; j++) {
                const uint32_t b0 = Vs[(k0    )*FP_ + j*8 + g];
                const uint32_t b1 = Vs[(k0 + 4)*FP_ + j*8 + g];
                mma_tf32(co[j], a, b0, b1);
            }
        }
    }

    // ---- finalize: /l, write directly to [B,S,D]
    const int bb = bh >> 4, h = bh & 15;
#pragma unroll
    for (int rr = 0; rr < 2; rr++) {
        const float inv = 1.0f / lrow[rr];
        const int srow = qi*64 + r0 + g + 8*rr;
        float* og = O + ((size_t)(bb*S_ + srow))*D_ + h*DK_;
#pragma unroll
        for (int j = 0; j < 8; j++) {
            float2 v = make_float2(co[j][2*rr]*inv, co[j][2*rr + 1]*inv);
            *(float2*)&og[j*8 + 2*t4] = v;
        }
    }
}

// ---------------------------------------------------------------------------
extern "C" void kernel_launch(void* const* d_in, const int* in_sizes, int n_in,
                              void* d_out, int out_size)
{
    const float* q   = (const float*)d_in[0];
    const float* k   = (const float*)d_in[1];
    const float* v   = (const float*)d_in[2];
    const float* w_q = (const float*)d_in[4];
    const float* b_q = (const float*)d_in[5];
    const float* w_k = (const float*)d_in[6];
    const float* b_k = (const float*)d_in[7];
    const float* w_v = (const float*)d_in[8];
    const float* b_v = (const float*)d_in[9];
    const float* w_o = (const float*)d_in[10];
    const float* b_o = (const float*)d_in[11];
    float* out = (float*)d_out;

    float *Qp, *Kp, *Vp, *AOp;
    cudaGetSymbolAddress((void**)&Qp,  g_Q);
    cudaGetSymbolAddress((void**)&Kp,  g_K);
    cudaGetSymbolAddress((void**)&Vp,  g_V);
    cudaGetSymbolAddress((void**)&AOp, g_AO);

    cudaFuncSetAttribute(gemm_mma<1>, cudaFuncAttributeMaxDynamicSharedMemorySize, SMEM_GEMM);
    cudaFuncSetAttribute(gemm_mma<0>, cudaFuncAttributeMaxDynamicSharedMemorySize, SMEM_GEMM);
    cudaFuncSetAttribute(flash_mma,   cudaFuncAttributeMaxDynamicSharedMemorySize, FLASH_SMEM);

    dim3 ggrid(D_/128, M_/128);   // 8 x 64
    gemm_mma<1><<<ggrid, 256, SMEM_GEMM>>>(q, w_q, b_q, Qp);
    gemm_mma<1><<<ggrid, 256, SMEM_GEMM>>>(k, w_k, b_k, Kp);
    gemm_mma<1><<<ggrid, 256, SMEM_GEMM>>>(v, w_v, b_v, Vp);

    flash_mma<<<dim3(S_/64, B_*H_), 128, FLASH_SMEM>>>(Qp, Kp, Vp, AOp);

    gemm_mma<0><<<ggrid, 256, SMEM_GEMM>>>(AOp, w_o, b_o, out);
}

// round 8
// speedup vs baseline: 2.9595x; 1.1083x over previous
#include <cuda_runtime.h>
#include <cstdint>
#include <math.h>

#define B_  4
#define S_  2048
#define D_  1024
#define H_  16
#define DK_ 64
#define M_  (B_*S_)   // 8192

// ---------------- scratch ---------------------------------------------------
__device__ float g_Q[M_*D_];   // [B,H,S,DK]
__device__ float g_K[M_*D_];   // [B,H,S,DK]
__device__ float g_V[M_*D_];   // [B,H,S,DK]
__device__ float g_AO[M_*D_];  // [B,S,D]

// ---------------- mma.sync helpers (compute_100-safe PTX, sm_80+) ----------
__device__ __forceinline__ uint32_t f2tf32(float f) {
    uint32_t o;
    asm("cvt.rna.tf32.f32 %0, %1;" : "=r"(o) : "f"(f));
    return o;
}
__device__ __forceinline__ void mma_tf32(float c[4], const uint32_t a[4],
                                         uint32_t b0, uint32_t b1) {
    asm volatile(
        "mma.sync.aligned.m16n8k8.row.col.f32.tf32.tf32.f32 "
        "{%0,%1,%2,%3}, {%4,%5,%6,%7}, {%8,%9}, {%0,%1,%2,%3};"
        : "+f"(c[0]), "+f"(c[1]), "+f"(c[2]), "+f"(c[3])
        : "r"(a[0]), "r"(a[1]), "r"(a[2]), "r"(a[3]), "r"(b0), "r"(b1));
}

// ---------------------------------------------------------------------------
// tf32 mma.sync NT GEMM: C = A@W^T + bias. CTA 128x128, BK=32, 8 warps.
// Round-8: proper pipelining — LDG(next) -> mma(cur) -> STS(next) -> sync.
// ---------------------------------------------------------------------------
#define BK_    32
#define KSTR   36
#define TBUF   (128*KSTR)
#define SMEM_GEMM (4*TBUF*4)              // 73728 B

template<int SCATTER>
__global__ void __launch_bounds__(256, 2) gemm_mma(
    const float* __restrict__ A, const float* __restrict__ W,
    const float* __restrict__ bias, float* __restrict__ out)
{
    extern __shared__ float sm[];   // [A0][B0][A1][B1]
    const int tid  = threadIdx.x;
    const int wid  = tid >> 5, lane = tid & 31;
    const int g    = lane >> 2, t4 = lane & 3;
    const int warpM = wid >> 1, warpN = wid & 1;
    const int bm = blockIdx.y, bn = blockIdx.x;

    float c[2][8][4];
#pragma unroll
    for (int i = 0; i < 2; i++)
#pragma unroll
        for (int j = 0; j < 8; j++)
#pragma unroll
            for (int r = 0; r < 4; r++) c[i][j][r] = 0.f;

    const float* Abase = A + (size_t)(bm*128)*D_;
    const float* Wbase = W + (size_t)(bn*128)*D_;
    const int r_ = tid >> 3, q_ = tid & 7;   // each thread: 4 rows (stride 32), 1 float4 col

    // prologue: stage tile 0
    {
#pragma unroll
        for (int u = 0; u < 4; u++) {
            const int r = r_ + u*32;
            float4 va = *(const float4*)(Abase + (size_t)r*D_ + q_*4);
            float4 vw = *(const float4*)(Wbase + (size_t)r*D_ + q_*4);
            uint32_t* da = (uint32_t*)(sm + 0*TBUF + r*KSTR + q_*4);
            uint32_t* dw = (uint32_t*)(sm + 1*TBUF + r*KSTR + q_*4);
            da[0]=f2tf32(va.x); da[1]=f2tf32(va.y); da[2]=f2tf32(va.z); da[3]=f2tf32(va.w);
            dw[0]=f2tf32(vw.x); dw[1]=f2tf32(vw.y); dw[2]=f2tf32(vw.z); dw[3]=f2tf32(vw.w);
        }
    }
    __syncthreads();

    const int NT = D_ / BK_;
    for (int kt = 0; kt < NT; ++kt) {
        const int cur = kt & 1;

        // issue LDGs for next tile (consumed only after the mma loop)
        float4 av[4], wv[4];
        if (kt + 1 < NT) {
#pragma unroll
            for (int u = 0; u < 4; u++) {
                const int r = r_ + u*32;
                av[u] = *(const float4*)(Abase + (size_t)r*D_ + (kt+1)*BK_ + q_*4);
                wv[u] = *(const float4*)(Wbase + (size_t)r*D_ + (kt+1)*BK_ + q_*4);
            }
        }

        const uint32_t* As = (const uint32_t*)(sm + (2*cur + 0)*TBUF);
        const uint32_t* Bs = (const uint32_t*)(sm + (2*cur + 1)*TBUF);
#pragma unroll
        for (int ks = 0; ks < 4; ++ks) {
            const int k0 = ks*8 + t4;
            uint32_t a[2][4];
#pragma unroll
            for (int i = 0; i < 2; i++) {
                const int mb = warpM*32 + i*16;
                a[i][0] = As[(mb + g    )*KSTR + k0    ];
                a[i][1] = As[(mb + 8 + g)*KSTR + k0    ];
                a[i][2] = As[(mb + g    )*KSTR + k0 + 4];
                a[i][3] = As[(mb + 8 + g)*KSTR + k0 + 4];
            }
#pragma unroll
            for (int j = 0; j < 8; j++) {
                const int nb = warpN*64 + j*8;
                const uint32_t b0 = Bs[(nb + g)*KSTR + k0    ];
                const uint32_t b1 = Bs[(nb + g)*KSTR + k0 + 4];
                mma_tf32(c[0][j], a[0], b0, b1);
                mma_tf32(c[1][j], a[1], b0, b1);
            }
        }

        if (kt + 1 < NT) {
            const int nxt = cur ^ 1;
#pragma unroll
            for (int u = 0; u < 4; u++) {
                const int r = r_ + u*32;
                uint32_t* da = (uint32_t*)(sm + (2*nxt + 0)*TBUF + r*KSTR + q_*4);
                uint32_t* dw = (uint32_t*)(sm + (2*nxt + 1)*TBUF + r*KSTR + q_*4);
                da[0]=f2tf32(av[u].x); da[1]=f2tf32(av[u].y); da[2]=f2tf32(av[u].z); da[3]=f2tf32(av[u].w);
                dw[0]=f2tf32(wv[u].x); dw[1]=f2tf32(wv[u].y); dw[2]=f2tf32(wv[u].z); dw[3]=f2tf32(wv[u].w);
            }
        }
        __syncthreads();
    }

#pragma unroll
    for (int i = 0; i < 2; i++) {
        const int mrow = bm*128 + warpM*32 + i*16 + g;
#pragma unroll
        for (int j = 0; j < 8; j++) {
            const int n = bn*128 + warpN*64 + j*8 + 2*t4;
            const float bx = __ldg(&bias[n]), by = __ldg(&bias[n+1]);
#pragma unroll
            for (int rr = 0; rr < 2; rr++) {
                const int m = mrow + rr*8;
                float2 v = make_float2(c[i][j][2*rr] + bx, c[i][j][2*rr+1] + by);
                if (SCATTER) {
                    const int bb = m >> 11, s = m & (S_-1);
                    const int h  = n >> 6,  dk = n & (DK_-1);
                    *(float2*)&out[((size_t)(bb*H_ + h)*S_ + s)*DK_ + dk] = v;
                } else {
                    *(float2*)&out[(size_t)m*D_ + n] = v;
                }
            }
        }
    }
}

// ---------------------------------------------------------------------------
// Flash attention on tensor cores, causal, 64x64 tiles, 4 warps.
// Round-8: Q A-fragments cached in registers for the whole kj loop; the Q
// SMEM buffer is then reused for P (Ps overlay) -> smem 52.2KB -> 4 CTA/SM.
// ---------------------------------------------------------------------------
#define FP_   68                            // padded row stride (words)
#define FLASH_SMEM (3*64*FP_*4)             // QP, K, V = 52224 B

__global__ void __launch_bounds__(128, 4) flash_mma(
    const float* __restrict__ Q, const float* __restrict__ K,
    const float* __restrict__ V, float* __restrict__ O)
{
    extern __shared__ uint32_t su[];
    uint32_t* QPs = su;                // [64][FP_]: Q during setup, then P
    uint32_t* Ks  = su + 64*FP_;       // [64][FP_] tf32, value K[k'][d]
    uint32_t* Vs  = su + 2*64*FP_;     // [64][FP_] tf32, value V[k'][d]

    const int qi  = blockIdx.x, bh = blockIdx.y;
    const int tid = threadIdx.x, wid = tid >> 5, lane = tid & 31;
    const int g   = lane >> 2, t4 = lane & 3;
    const int r0  = wid*16;

    // stage Q (scaled 1/sqrt(DK)=0.125, tf32)
    const float* qg = Q + (size_t)(bh*S_ + qi*64) * DK_;
#pragma unroll
    for (int f = tid; f < 1024; f += 128) {
        const int r = f >> 4, c4 = (f & 15) << 2;
        float4 v = ((const float4*)qg)[f];
        QPs[r*FP_ + c4 + 0] = f2tf32(v.x*0.125f);
        QPs[r*FP_ + c4 + 1] = f2tf32(v.y*0.125f);
        QPs[r*FP_ + c4 + 2] = f2tf32(v.z*0.125f);
        QPs[r*FP_ + c4 + 3] = f2tf32(v.w*0.125f);
    }
    __syncthreads();

    // extract Q A-fragments once (reused for all kj): 8 ksteps x 4 regs
    uint32_t qa[8][4];
#pragma unroll
    for (int ks = 0; ks < 8; ++ks) {
        const int k0 = ks*8 + t4;
        qa[ks][0] = QPs[(r0 + g    )*FP_ + k0    ];
        qa[ks][1] = QPs[(r0 + 8 + g)*FP_ + k0    ];
        qa[ks][2] = QPs[(r0 + g    )*FP_ + k0 + 4];
        qa[ks][3] = QPs[(r0 + 8 + g)*FP_ + k0 + 4];
    }

    float co[8][4];
#pragma unroll
    for (int j = 0; j < 8; j++)
#pragma unroll
        for (int r = 0; r < 4; r++) co[j][r] = 0.f;
    float mrow[2] = {-INFINITY, -INFINITY};
    float lrow[2] = {0.f, 0.f};

    for (int kj = 0; kj <= qi; ++kj) {
        __syncthreads();   // Ks/Vs of prev iter consumed; also orders Q-frag
                           // extraction (pre-loop) before first P overlay write

        const float* kg = K + (size_t)(bh*S_ + kj*64) * DK_;
        const float* vg = V + (size_t)(bh*S_ + kj*64) * DK_;
#pragma unroll
        for (int f = tid; f < 1024; f += 128) {
            const int r = f >> 4, c4 = (f & 15) << 2;
            float4 kv = ((const float4*)kg)[f];
            Ks[r*FP_ + c4 + 0] = f2tf32(kv.x);
            Ks[r*FP_ + c4 + 1] = f2tf32(kv.y);
            Ks[r*FP_ + c4 + 2] = f2tf32(kv.z);
            Ks[r*FP_ + c4 + 3] = f2tf32(kv.w);
            float4 vv = ((const float4*)vg)[f];
            Vs[r*FP_ + c4 + 0] = f2tf32(vv.x);
            Vs[r*FP_ + c4 + 1] = f2tf32(vv.y);
            Vs[r*FP_ + c4 + 2] = f2tf32(vv.z);
            Vs[r*FP_ + c4 + 3] = f2tf32(vv.w);
        }
        __syncthreads();

        // ---- S = Q @ K^T (A-frags from registers)
        float cs[8][4];
#pragma unroll
        for (int j = 0; j < 8; j++)
#pragma unroll
            for (int r = 0; r < 4; r++) cs[j][r] = 0.f;
#pragma unroll
        for (int ks = 0; ks < 8; ++ks) {
            const int k0 = ks*8 + t4;
#pragma unroll
            for (int j = 0; j < 8; j++) {
                const uint32_t b0 = Ks[(j*8 + g)*FP_ + k0    ];
                const uint32_t b1 = Ks[(j*8 + g)*FP_ + k0 + 4];
                mma_tf32(cs[j], qa[ks], b0, b1);
            }
        }

        // ---- causal mask on diagonal tile
        if (kj == qi) {
#pragma unroll
            for (int j = 0; j < 8; j++)
#pragma unroll
                for (int rr = 0; rr < 2; rr++)
#pragma unroll
                    for (int e = 0; e < 2; e++) {
                        const int row = r0 + g + 8*rr;
                        const int col = j*8 + 2*t4 + e;
                        if (col > row) cs[j][2*rr + e] = -1e30f;
                    }
        }

        // ---- online softmax (quad reduction)
#pragma unroll
        for (int rr = 0; rr < 2; rr++) {
            float mt = -INFINITY;
#pragma unroll
            for (int j = 0; j < 8; j++)
                mt = fmaxf(mt, fmaxf(cs[j][2*rr], cs[j][2*rr + 1]));
            mt = fmaxf(mt, __shfl_xor_sync(0xffffffffu, mt, 1));
            mt = fmaxf(mt, __shfl_xor_sync(0xffffffffu, mt, 2));
            const float mn   = fmaxf(mrow[rr], mt);
            const float corr = __expf(mrow[rr] - mn);
            float ls = 0.f;
#pragma unroll
            for (int j = 0; j < 8; j++) {
                const float p0 = __expf(cs[j][2*rr    ] - mn);
                const float p1 = __expf(cs[j][2*rr + 1] - mn);
                cs[j][2*rr] = p0; cs[j][2*rr + 1] = p1;
                ls += p0 + p1;
            }
            ls += __shfl_xor_sync(0xffffffffu, ls, 1);
            ls += __shfl_xor_sync(0xffffffffu, ls, 2);
            lrow[rr] = lrow[rr]*corr + ls;
            mrow[rr] = mn;
#pragma unroll
            for (int j = 0; j < 8; j++) {
                co[j][2*rr] *= corr; co[j][2*rr + 1] *= corr;
            }
        }

        // ---- P -> QPs overlay (warp-local rows only)
#pragma unroll
        for (int rr = 0; rr < 2; rr++) {
            const int row = r0 + g + 8*rr;
#pragma unroll
            for (int j = 0; j < 8; j++) {
                const int idx = row*FP_ + j*8 + 2*t4;
                QPs[idx    ] = f2tf32(cs[j][2*rr    ]);
                QPs[idx + 1] = f2tf32(cs[j][2*rr + 1]);
            }
        }
        __syncwarp();

        // ---- O += P @ V
#pragma unroll
        for (int ks = 0; ks < 8; ++ks) {
            const int k0 = ks*8 + t4;
            uint32_t a[4];
            a[0] = QPs[(r0 + g    )*FP_ + k0    ];
            a[1] = QPs[(r0 + 8 + g)*FP_ + k0    ];
            a[2] = QPs[(r0 + g    )*FP_ + k0 + 4];
            a[3] = QPs[(r0 + 8 + g)*FP_ + k0 + 4];
#pragma unroll
            for (int j = 0; j < 8; j++) {
                const uint32_t b0 = Vs[(k0    )*FP_ + j*8 + g];
                const uint32_t b1 = Vs[(k0 + 4)*FP_ + j*8 + g];
                mma_tf32(co[j], a, b0, b1);
            }
        }
    }

    // ---- finalize: /l, write to [B,S,D]
    const int bb = bh >> 4, h = bh & 15;
#pragma unroll
    for (int rr = 0; rr < 2; rr++) {
        const float inv = 1.0f / lrow[rr];
        const int srow = qi*64 + r0 + g + 8*rr;
        float* og = O + ((size_t)(bb*S_ + srow))*D_ + h*DK_;
#pragma unroll
        for (int j = 0; j < 8; j++) {
            float2 v = make_float2(co[j][2*rr]*inv, co[j][2*rr + 1]*inv);
            *(float2*)&og[j*8 + 2*t4] = v;
        }
    }
}

// ---------------------------------------------------------------------------
extern "C" void kernel_launch(void* const* d_in, const int* in_sizes, int n_in,
                              void* d_out, int out_size)
{
    const float* q   = (const float*)d_in[0];
    const float* k   = (const float*)d_in[1];
    const float* v   = (const float*)d_in[2];
    const float* w_q = (const float*)d_in[4];
    const float* b_q = (const float*)d_in[5];
    const float* w_k = (const float*)d_in[6];
    const float* b_k = (const float*)d_in[7];
    const float* w_v = (const float*)d_in[8];
    const float* b_v = (const float*)d_in[9];
    const float* w_o = (const float*)d_in[10];
    const float* b_o = (const float*)d_in[11];
    float* out = (float*)d_out;

    float *Qp, *Kp, *Vp, *AOp;
    cudaGetSymbolAddress((void**)&Qp,  g_Q);
    cudaGetSymbolAddress((void**)&Kp,  g_K);
    cudaGetSymbolAddress((void**)&Vp,  g_V);
    cudaGetSymbolAddress((void**)&AOp, g_AO);

    cudaFuncSetAttribute(gemm_mma<1>, cudaFuncAttributeMaxDynamicSharedMemorySize, SMEM_GEMM);
    cudaFuncSetAttribute(gemm_mma<0>, cudaFuncAttributeMaxDynamicSharedMemorySize, SMEM_GEMM);
    cudaFuncSetAttribute(flash_mma,   cudaFuncAttributeMaxDynamicSharedMemorySize, FLASH_SMEM);

    dim3 ggrid(D_/128, M_/128);   // 8 x 64
    gemm_mma<1><<<ggrid, 256, SMEM_GEMM>>>(q, w_q, b_q, Qp);
    gemm_mma<1><<<ggrid, 256, SMEM_GEMM>>>(k, w_k, b_k, Kp);
    gemm_mma<1><<<ggrid, 256, SMEM_GEMM>>>(v, w_v, b_v, Vp);

    flash_mma<<<dim3(S_/64, B_*H_), 128, FLASH_SMEM>>>(Qp, Kp, Vp, AOp);

    gemm_mma<0><<<ggrid, 256, SMEM_GEMM>>>(AOp, w_o, b_o, out);
}

// round 9
// speedup vs baseline: 3.2421x; 1.0955x over previous
#include <cuda_runtime.h>
#include <cstdint>
#include <math.h>

#define B_  4
#define S_  2048
#define D_  1024
#define H_  16
#define DK_ 64
#define M_  (B_*S_)   // 8192

// ---------------- scratch ---------------------------------------------------
__device__ float g_Q[M_*D_];   // [B,H,S,DK]
__device__ float g_K[M_*D_];   // [B,H,S,DK]
__device__ float g_V[M_*D_];   // [B,H,S,DK]
__device__ float g_AO[M_*D_];  // [B,S,D]

// ---------------- mma.sync helpers (compute_100-safe PTX, sm_80+) ----------
__device__ __forceinline__ uint32_t f2tf32(float f) {
    uint32_t o;
    asm("cvt.rna.tf32.f32 %0, %1;" : "=r"(o) : "f"(f));
    return o;
}
__device__ __forceinline__ void mma_tf32(float c[4], const uint32_t a[4],
                                         uint32_t b0, uint32_t b1) {
    asm volatile(
        "mma.sync.aligned.m16n8k8.row.col.f32.tf32.tf32.f32 "
        "{%0,%1,%2,%3}, {%4,%5,%6,%7}, {%8,%9}, {%0,%1,%2,%3};"
        : "+f"(c[0]), "+f"(c[1]), "+f"(c[2]), "+f"(c[3])
        : "r"(a[0]), "r"(a[1]), "r"(a[2]), "r"(a[3]), "r"(b0), "r"(b1));
}

// ---------------------------------------------------------------------------
// tf32 mma.sync NT GEMM (round-8 proven, + uint4 staging STS)
// CTA 128x128, BK=32, 8 warps (4Mx2N), warp tile 32x64, double-buffered.
// ---------------------------------------------------------------------------
#define BK_    32
#define KSTR   36
#define TBUF   (128*KSTR)
#define SMEM_GEMM (4*TBUF*4)              // 73728 B

template<int SCATTER>
__global__ void __launch_bounds__(256, 2) gemm_mma(
    const float* __restrict__ A, const float* __restrict__ W,
    const float* __restrict__ bias, float* __restrict__ out)
{
    extern __shared__ float sm[];   // [A0][B0][A1][B1]
    const int tid  = threadIdx.x;
    const int wid  = tid >> 5, lane = tid & 31;
    const int g    = lane >> 2, t4 = lane & 3;
    const int warpM = wid >> 1, warpN = wid & 1;
    const int bm = blockIdx.y, bn = blockIdx.x;

    float c[2][8][4];
#pragma unroll
    for (int i = 0; i < 2; i++)
#pragma unroll
        for (int j = 0; j < 8; j++)
#pragma unroll
            for (int r = 0; r < 4; r++) c[i][j][r] = 0.f;

    const float* Abase = A + (size_t)(bm*128)*D_;
    const float* Wbase = W + (size_t)(bn*128)*D_;
    const int r_ = tid >> 3, q_ = tid & 7;

    {
#pragma unroll
        for (int u = 0; u < 4; u++) {
            const int r = r_ + u*32;
            float4 va = *(const float4*)(Abase + (size_t)r*D_ + q_*4);
            float4 vw = *(const float4*)(Wbase + (size_t)r*D_ + q_*4);
            uint4 ta = make_uint4(f2tf32(va.x), f2tf32(va.y), f2tf32(va.z), f2tf32(va.w));
            uint4 tw = make_uint4(f2tf32(vw.x), f2tf32(vw.y), f2tf32(vw.z), f2tf32(vw.w));
            *(uint4*)((uint32_t*)(sm + 0*TBUF) + r*KSTR + q_*4) = ta;
            *(uint4*)((uint32_t*)(sm + 1*TBUF) + r*KSTR + q_*4) = tw;
        }
    }
    __syncthreads();

    const int NT = D_ / BK_;
    for (int kt = 0; kt < NT; ++kt) {
        const int cur = kt & 1;

        float4 av[4], wv[4];
        if (kt + 1 < NT) {
#pragma unroll
            for (int u = 0; u < 4; u++) {
                const int r = r_ + u*32;
                av[u] = *(const float4*)(Abase + (size_t)r*D_ + (kt+1)*BK_ + q_*4);
                wv[u] = *(const float4*)(Wbase + (size_t)r*D_ + (kt+1)*BK_ + q_*4);
            }
        }

        const uint32_t* As = (const uint32_t*)(sm + (2*cur + 0)*TBUF);
        const uint32_t* Bs = (const uint32_t*)(sm + (2*cur + 1)*TBUF);
#pragma unroll
        for (int ks = 0; ks < 4; ++ks) {
            const int k0 = ks*8 + t4;
            uint32_t a[2][4];
#pragma unroll
            for (int i = 0; i < 2; i++) {
                const int mb = warpM*32 + i*16;
                a[i][0] = As[(mb + g    )*KSTR + k0    ];
                a[i][1] = As[(mb + 8 + g)*KSTR + k0    ];
                a[i][2] = As[(mb + g    )*KSTR + k0 + 4];
                a[i][3] = As[(mb + 8 + g)*KSTR + k0 + 4];
            }
#pragma unroll
            for (int j = 0; j < 8; j++) {
                const int nb = warpN*64 + j*8;
                const uint32_t b0 = Bs[(nb + g)*KSTR + k0    ];
                const uint32_t b1 = Bs[(nb + g)*KSTR + k0 + 4];
                mma_tf32(c[0][j], a[0], b0, b1);
                mma_tf32(c[1][j], a[1], b0, b1);
            }
        }

        if (kt + 1 < NT) {
            const int nxt = cur ^ 1;
#pragma unroll
            for (int u = 0; u < 4; u++) {
                const int r = r_ + u*32;
                uint4 ta = make_uint4(f2tf32(av[u].x), f2tf32(av[u].y), f2tf32(av[u].z), f2tf32(av[u].w));
                uint4 tw = make_uint4(f2tf32(wv[u].x), f2tf32(wv[u].y), f2tf32(wv[u].z), f2tf32(wv[u].w));
                *(uint4*)((uint32_t*)(sm + (2*nxt + 0)*TBUF) + r*KSTR + q_*4) = ta;
                *(uint4*)((uint32_t*)(sm + (2*nxt + 1)*TBUF) + r*KSTR + q_*4) = tw;
            }
        }
        __syncthreads();
    }

#pragma unroll
    for (int i = 0; i < 2; i++) {
        const int mrow = bm*128 + warpM*32 + i*16 + g;
#pragma unroll
        for (int j = 0; j < 8; j++) {
            const int n = bn*128 + warpN*64 + j*8 + 2*t4;
            const float bx = __ldg(&bias[n]), by = __ldg(&bias[n+1]);
#pragma unroll
            for (int rr = 0; rr < 2; rr++) {
                const int m = mrow + rr*8;
                float2 v = make_float2(c[i][j][2*rr] + bx, c[i][j][2*rr+1] + by);
                if (SCATTER) {
                    const int bb = m >> 11, s = m & (S_-1);
                    const int h  = n >> 6,  dk = n & (DK_-1);
                    *(float2*)&out[((size_t)(bb*H_ + h)*S_ + s)*DK_ + dk] = v;
                } else {
                    *(float2*)&out[(size_t)m*D_ + n] = v;
                }
            }
        }
    }
}

// ---------------------------------------------------------------------------
// Flash attention, tf32 mma.sync, causal.
// Round-9: 128-row Q tile, 4 warps x 32 rows (two 16-row halves per warp),
// B-fragments (K and V) loaded ONCE per (ks,j) and reused for both halves.
// Q A-frags for both halves cached in registers; P overlays Q SMEM.
// K tile stays 64 -> loop kj = 0..2*qi+1, diagonal masking via dcol.
// ---------------------------------------------------------------------------
#define FP_   68                            // padded row stride (words)
#define FLASH_SMEM ((128 + 64 + 64)*FP_*4)  // QP(128) + K(64) + V(64) = 69632 B

__global__ void __launch_bounds__(128, 2) flash_mma(
    const float* __restrict__ Q, const float* __restrict__ K,
    const float* __restrict__ V, float* __restrict__ O)
{
    extern __shared__ uint32_t su[];
    uint32_t* QPs = su;                 // [128][FP_]: Q during setup, then P
    uint32_t* Ks  = su + 128*FP_;       // [64][FP_]  K[k'][d]
    uint32_t* Vs  = su + 192*FP_;       // [64][FP_]  V[k'][d]

    const int qi  = blockIdx.x, bh = blockIdx.y;   // qi: 128-row query tile
    const int tid = threadIdx.x, wid = tid >> 5, lane = tid & 31;
    const int g   = lane >> 2, t4 = lane & 3;
    const int r0  = wid*32;                         // warp's 32 query rows

    // stage Q (scaled 1/sqrt(DK)=0.125, tf32), 128 rows
    const float* qg = Q + (size_t)(bh*S_ + qi*128) * DK_;
#pragma unroll
    for (int f = tid; f < 2048; f += 128) {
        const int r = f >> 4, c4 = (f & 15) << 2;
        float4 v = ((const float4*)qg)[f];
        *(uint4*)&QPs[r*FP_ + c4] = make_uint4(
            f2tf32(v.x*0.125f), f2tf32(v.y*0.125f),
            f2tf32(v.z*0.125f), f2tf32(v.w*0.125f));
    }
    __syncthreads();

    // cache Q A-fragments for both 16-row halves (whole kj loop)
    uint32_t qa[2][8][4];
#pragma unroll
    for (int h = 0; h < 2; h++) {
        const int rb = r0 + h*16;
#pragma unroll
        for (int ks = 0; ks < 8; ++ks) {
            const int k0 = ks*8 + t4;
            qa[h][ks][0] = QPs[(rb + g    )*FP_ + k0    ];
            qa[h][ks][1] = QPs[(rb + 8 + g)*FP_ + k0    ];
            qa[h][ks][2] = QPs[(rb + g    )*FP_ + k0 + 4];
            qa[h][ks][3] = QPs[(rb + 8 + g)*FP_ + k0 + 4];
        }
    }

    float co[2][8][4];
#pragma unroll
    for (int h = 0; h < 2; h++)
#pragma unroll
        for (int j = 0; j < 8; j++)
#pragma unroll
            for (int r = 0; r < 4; r++) co[h][j][r] = 0.f;
    float mrow[2][2] = {{-INFINITY,-INFINITY},{-INFINITY,-INFINITY}};
    float lrow[2][2] = {{0.f,0.f},{0.f,0.f}};

    const int kmax = 2*qi + 1;
    for (int kj = 0; kj <= kmax; ++kj) {
        __syncthreads();   // all warps done reading Ks/Vs of prev iter

        const float* kg = K + (size_t)(bh*S_ + kj*64) * DK_;
        const float* vg = V + (size_t)(bh*S_ + kj*64) * DK_;
#pragma unroll
        for (int f = tid; f < 1024; f += 128) {
            const int r = f >> 4, c4 = (f & 15) << 2;
            float4 kv = ((const float4*)kg)[f];
            *(uint4*)&Ks[r*FP_ + c4] = make_uint4(
                f2tf32(kv.x), f2tf32(kv.y), f2tf32(kv.z), f2tf32(kv.w));
            float4 vv = ((const float4*)vg)[f];
            *(uint4*)&Vs[r*FP_ + c4] = make_uint4(
                f2tf32(vv.x), f2tf32(vv.y), f2tf32(vv.z), f2tf32(vv.w));
        }
        __syncthreads();

        // ---- S = Q @ K^T for both halves; B-frags loaded once
        float cs[2][8][4];
#pragma unroll
        for (int h = 0; h < 2; h++)
#pragma unroll
            for (int j = 0; j < 8; j++)
#pragma unroll
                for (int r = 0; r < 4; r++) cs[h][j][r] = 0.f;
#pragma unroll
        for (int ks = 0; ks < 8; ++ks) {
            const int k0 = ks*8 + t4;
#pragma unroll
            for (int j = 0; j < 8; j++) {
                const uint32_t b0 = Ks[(j*8 + g)*FP_ + k0    ];
                const uint32_t b1 = Ks[(j*8 + g)*FP_ + k0 + 4];
                mma_tf32(cs[0][j], qa[0][ks], b0, b1);
                mma_tf32(cs[1][j], qa[1][ks], b0, b1);
            }
        }

        // ---- causal mask (only the last two k-tiles can clip)
        if (kj >= 2*qi) {
            const int dcol = (kj - 2*qi)*64;
#pragma unroll
            for (int h = 0; h < 2; h++)
#pragma unroll
                for (int j = 0; j < 8; j++)
#pragma unroll
                    for (int rr = 0; rr < 2; rr++)
#pragma unroll
                        for (int e = 0; e < 2; e++) {
                            const int row = r0 + h*16 + g + 8*rr;
                            const int col = dcol + j*8 + 2*t4 + e;
                            if (col > row) cs[h][j][2*rr + e] = -1e30f;
                        }
        }

        // ---- online softmax per half, per row-pair (quad reduction)
#pragma unroll
        for (int h = 0; h < 2; h++)
#pragma unroll
        for (int rr = 0; rr < 2; rr++) {
            float mt = -INFINITY;
#pragma unroll
            for (int j = 0; j < 8; j++)
                mt = fmaxf(mt, fmaxf(cs[h][j][2*rr], cs[h][j][2*rr + 1]));
            mt = fmaxf(mt, __shfl_xor_sync(0xffffffffu, mt, 1));
            mt = fmaxf(mt, __shfl_xor_sync(0xffffffffu, mt, 2));
            const float mn   = fmaxf(mrow[h][rr], mt);
            const float corr = __expf(mrow[h][rr] - mn);
            float ls = 0.f;
#pragma unroll
            for (int j = 0; j < 8; j++) {
                const float p0 = __expf(cs[h][j][2*rr    ] - mn);
                const float p1 = __expf(cs[h][j][2*rr + 1] - mn);
                cs[h][j][2*rr] = p0; cs[h][j][2*rr + 1] = p1;
                ls += p0 + p1;
            }
            ls += __shfl_xor_sync(0xffffffffu, ls, 1);
            ls += __shfl_xor_sync(0xffffffffu, ls, 2);
            lrow[h][rr] = lrow[h][rr]*corr + ls;
            mrow[h][rr] = mn;
#pragma unroll
            for (int j = 0; j < 8; j++) {
                co[h][j][2*rr] *= corr; co[h][j][2*rr + 1] *= corr;
            }
        }

        // ---- P -> QPs overlay (warp-local rows), uint2 stores
#pragma unroll
        for (int h = 0; h < 2; h++)
#pragma unroll
        for (int rr = 0; rr < 2; rr++) {
            const int row = r0 + h*16 + g + 8*rr;
#pragma unroll
            for (int j = 0; j < 8; j++) {
                *(uint2*)&QPs[row*FP_ + j*8 + 2*t4] = make_uint2(
                    f2tf32(cs[h][j][2*rr]), f2tf32(cs[h][j][2*rr + 1]));
            }
        }
        __syncwarp();

        // ---- O += P @ V; B-frags loaded once, A-frags per half
#pragma unroll
        for (int ks = 0; ks < 8; ++ks) {
            const int k0 = ks*8 + t4;
            uint32_t a0[4], a1[4];
            a0[0] = QPs[(r0 + g     )*FP_ + k0    ];
            a0[1] = QPs[(r0 + 8 + g )*FP_ + k0    ];
            a0[2] = QPs[(r0 + g     )*FP_ + k0 + 4];
            a0[3] = QPs[(r0 + 8 + g )*FP_ + k0 + 4];
            a1[0] = QPs[(r0 + 16 + g)*FP_ + k0    ];
            a1[1] = QPs[(r0 + 24 + g)*FP_ + k0    ];
            a1[2] = QPs[(r0 + 16 + g)*FP_ + k0 + 4];
            a1[3] = QPs[(r0 + 24 + g)*FP_ + k0 + 4];
#pragma unroll
            for (int j = 0; j < 8; j++) {
                const uint32_t b0 = Vs[(k0    )*FP_ + j*8 + g];
                const uint32_t b1 = Vs[(k0 + 4)*FP_ + j*8 + g];
                mma_tf32(co[0][j], a0, b0, b1);
                mma_tf32(co[1][j], a1, b0, b1);
            }
        }
    }

    // ---- finalize: /l, write to [B,S,D]
    const int bb = bh >> 4, h16 = bh & 15;
#pragma unroll
    for (int h = 0; h < 2; h++)
#pragma unroll
    for (int rr = 0; rr < 2; rr++) {
        const float inv = 1.0f / lrow[h][rr];
        const int srow = qi*128 + r0 + h*16 + g + 8*rr;
        float* og = O + ((size_t)(bb*S_ + srow))*D_ + h16*DK_;
#pragma unroll
        for (int j = 0; j < 8; j++) {
            *(float2*)&og[j*8 + 2*t4] = make_float2(
                co[h][j][2*rr]*inv, co[h][j][2*rr + 1]*inv);
        }
    }
}

// ---------------------------------------------------------------------------
extern "C" void kernel_launch(void* const* d_in, const int* in_sizes, int n_in,
                              void* d_out, int out_size)
{
    const float* q   = (const float*)d_in[0];
    const float* k   = (const float*)d_in[1];
    const float* v   = (const float*)d_in[2];
    const float* w_q = (const float*)d_in[4];
    const float* b_q = (const float*)d_in[5];
    const float* w_k = (const float*)d_in[6];
    const float* b_k = (const float*)d_in[7];
    const float* w_v = (const float*)d_in[8];
    const float* b_v = (const float*)d_in[9];
    const float* w_o = (const float*)d_in[10];
    const float* b_o = (const float*)d_in[11];
    float* out = (float*)d_out;

    float *Qp, *Kp, *Vp, *AOp;
    cudaGetSymbolAddress((void**)&Qp,  g_Q);
    cudaGetSymbolAddress((void**)&Kp,  g_K);
    cudaGetSymbolAddress((void**)&Vp,  g_V);
    cudaGetSymbolAddress((void**)&AOp, g_AO);

    cudaFuncSetAttribute(gemm_mma<1>, cudaFuncAttributeMaxDynamicSharedMemorySize, SMEM_GEMM);
    cudaFuncSetAttribute(gemm_mma<0>, cudaFuncAttributeMaxDynamicSharedMemorySize, SMEM_GEMM);
    cudaFuncSetAttribute(flash_mma,   cudaFuncAttributeMaxDynamicSharedMemorySize, FLASH_SMEM);

    dim3 ggrid(D_/128, M_/128);   // 8 x 64
    gemm_mma<1><<<ggrid, 256, SMEM_GEMM>>>(q, w_q, b_q, Qp);
    gemm_mma<1><<<ggrid, 256, SMEM_GEMM>>>(k, w_k, b_k, Kp);
    gemm_mma<1><<<ggrid, 256, SMEM_GEMM>>>(v, w_v, b_v, Vp);

    flash_mma<<<dim3(S_/128, B_*H_), 128, FLASH_SMEM>>>(Qp, Kp, Vp, AOp);

    gemm_mma<0><<<ggrid, 256, SMEM_GEMM>>>(AOp, w_o, b_o, out);
}

// round 10
// speedup vs baseline: 4.8617x; 1.4995x over previous
#include <cuda_runtime.h>
#include <cuda_fp16.h>
#include <cstdint>
#include <math.h>

#define B_  4
#define S_  2048
#define D_  1024
#define H_  16
#define DK_ 64
#define M_  (B_*S_)   // 8192

// ---------------- scratch ---------------------------------------------------
__device__ float g_Q[M_*D_];   // [B,H,S,DK]
__device__ float g_K[M_*D_];   // [B,H,S,DK]
__device__ float g_V[M_*D_];   // [B,H,S,DK]
__device__ float g_AO[M_*D_];  // [B,S,D]

// ---------------- fp16 mma.sync helpers (sm_80+ PTX, compute_100-safe) -----
__device__ __forceinline__ uint32_t pack_h2(float x, float y) {
    __half2 h = __float22half2_rn(make_float2(x, y));
    return *reinterpret_cast<uint32_t*>(&h);
}
__device__ __forceinline__ void mma_f16(float c[4], const uint32_t a[4],
                                        uint32_t b0, uint32_t b1) {
    asm volatile(
        "mma.sync.aligned.m16n8k16.row.col.f32.f16.f16.f32 "
        "{%0,%1,%2,%3}, {%4,%5,%6,%7}, {%8,%9}, {%0,%1,%2,%3};"
        : "+f"(c[0]), "+f"(c[1]), "+f"(c[2]), "+f"(c[3])
        : "r"(a[0]), "r"(a[1]), "r"(a[2]), "r"(a[3]), "r"(b0), "r"(b1));
}

// ---------------------------------------------------------------------------
// fp16 mma.sync NT GEMM: C = A@W^T + bias (fp32 accum).
// CTA 128x128, BK=32, 8 warps (4Mx2N), warp tile 32x64, double-buffered.
// SMEM rows padded to 40 halves -> conflict-free frag LDS (bank=20g+t4).
// ---------------------------------------------------------------------------
#define BK_    32
#define KSH    40                         // halves per padded row
#define TBUFH  (128*KSH)                  // halves per tile buffer
#define SMEM_GEMM (4*TBUFH*2)             // A0,B0,A1,B1 = 40960 B

template<int SCATTER>
__global__ void __launch_bounds__(256, 2) gemm_mma(
    const float* __restrict__ A, const float* __restrict__ W,
    const float* __restrict__ bias, float* __restrict__ out)
{
    extern __shared__ __half smh[];   // [A0][B0][A1][B1]
    const int tid  = threadIdx.x;
    const int wid  = tid >> 5, lane = tid & 31;
    const int g    = lane >> 2, t4 = lane & 3;
    const int warpM = wid >> 1, warpN = wid & 1;
    const int bm = blockIdx.y, bn = blockIdx.x;

    float c[2][8][4];
#pragma unroll
    for (int i = 0; i < 2; i++)
#pragma unroll
        for (int j = 0; j < 8; j++)
#pragma unroll
            for (int r = 0; r < 4; r++) c[i][j][r] = 0.f;

    const float* Abase = A + (size_t)(bm*128)*D_;
    const float* Wbase = W + (size_t)(bn*128)*D_;
    const int r_ = tid >> 3, q_ = tid & 7;   // 4 rows/thread (stride 32), 1 float4 col

    // prologue: stage tile 0 (gmem fp32 -> half, uint2 STS)
    {
#pragma unroll
        for (int u = 0; u < 4; u++) {
            const int r = r_ + u*32;
            float4 va = *(const float4*)(Abase + (size_t)r*D_ + q_*4);
            float4 vw = *(const float4*)(Wbase + (size_t)r*D_ + q_*4);
            *(uint2*)&smh[0*TBUFH + r*KSH + q_*4] =
                make_uint2(pack_h2(va.x, va.y), pack_h2(va.z, va.w));
            *(uint2*)&smh[1*TBUFH + r*KSH + q_*4] =
                make_uint2(pack_h2(vw.x, vw.y), pack_h2(vw.z, vw.w));
        }
    }
    __syncthreads();

    const int NT = D_ / BK_;
    for (int kt = 0; kt < NT; ++kt) {
        const int cur = kt & 1;

        float4 av[4], wv[4];
        if (kt + 1 < NT) {
#pragma unroll
            for (int u = 0; u < 4; u++) {
                const int r = r_ + u*32;
                av[u] = *(const float4*)(Abase + (size_t)r*D_ + (kt+1)*BK_ + q_*4);
                wv[u] = *(const float4*)(Wbase + (size_t)r*D_ + (kt+1)*BK_ + q_*4);
            }
        }

        const __half* As = smh + (2*cur + 0)*TBUFH;
        const __half* Bs = smh + (2*cur + 1)*TBUFH;
#pragma unroll
        for (int ks = 0; ks < 2; ++ks) {           // two k16 steps per BK=32
            const int k0 = ks*16 + 2*t4;
            uint32_t a[2][4];
#pragma unroll
            for (int i = 0; i < 2; i++) {
                const int mb = warpM*32 + i*16;
                a[i][0] = *(const uint32_t*)&As[(mb + g    )*KSH + k0    ];
                a[i][1] = *(const uint32_t*)&As[(mb + 8 + g)*KSH + k0    ];
                a[i][2] = *(const uint32_t*)&As[(mb + g    )*KSH + k0 + 8];
                a[i][3] = *(const uint32_t*)&As[(mb + 8 + g)*KSH + k0 + 8];
            }
#pragma unroll
            for (int j = 0; j < 8; j++) {
                const int nb = warpN*64 + j*8;
                const uint32_t b0 = *(const uint32_t*)&Bs[(nb + g)*KSH + k0    ];
                const uint32_t b1 = *(const uint32_t*)&Bs[(nb + g)*KSH + k0 + 8];
                mma_f16(c[0][j], a[0], b0, b1);
                mma_f16(c[1][j], a[1], b0, b1);
            }
        }

        if (kt + 1 < NT) {
            const int nxt = cur ^ 1;
#pragma unroll
            for (int u = 0; u < 4; u++) {
                const int r = r_ + u*32;
                *(uint2*)&smh[(2*nxt + 0)*TBUFH + r*KSH + q_*4] =
                    make_uint2(pack_h2(av[u].x, av[u].y), pack_h2(av[u].z, av[u].w));
                *(uint2*)&smh[(2*nxt + 1)*TBUFH + r*KSH + q_*4] =
                    make_uint2(pack_h2(wv[u].x, wv[u].y), pack_h2(wv[u].z, wv[u].w));
            }
        }
        __syncthreads();
    }

#pragma unroll
    for (int i = 0; i < 2; i++) {
        const int mrow = bm*128 + warpM*32 + i*16 + g;
#pragma unroll
        for (int j = 0; j < 8; j++) {
            const int n = bn*128 + warpN*64 + j*8 + 2*t4;
            const float bx = __ldg(&bias[n]), by = __ldg(&bias[n+1]);
#pragma unroll
            for (int rr = 0; rr < 2; rr++) {
                const int m = mrow + rr*8;
                float2 v = make_float2(c[i][j][2*rr] + bx, c[i][j][2*rr+1] + by);
                if (SCATTER) {
                    const int bb = m >> 11, s = m & (S_-1);
                    const int h  = n >> 6,  dk = n & (DK_-1);
                    *(float2*)&out[((size_t)(bb*H_ + h)*S_ + s)*DK_ + dk] = v;
                } else {
                    *(float2*)&out[(size_t)m*D_ + n] = v;
                }
            }
        }
    }
}

// ---------------------------------------------------------------------------
// Flash attention, fp16 mma.sync m16n8k16, causal.
// 128-row Q tile, 4 warps x 32 rows (two 16-row halves), shared B-frags.
// Q staged in Ps then register-cached (32 regs); P overlays Ps buffer.
// K,V both NATURAL [key][d] layout, row stride 72 halves.
//   QK^T B-frag: half2 along d           -> conflict-free 32-bit LDS.
//   PV   B-frag: pair of 16-bit LDS (k,k+1 rows) -> word-merged, conflict-free.
// ---------------------------------------------------------------------------
#define PKS   72                            // padded row stride (halves)
#define FLASH_SMEM ((128 + 64 + 64)*PKS*2)  // Ps(128)+Ks(64)+Vs(64) = 36864 B

__global__ void __launch_bounds__(128, 2) flash_mma(
    const float* __restrict__ Q, const float* __restrict__ K,
    const float* __restrict__ V, float* __restrict__ O)
{
    extern __shared__ __half sh[];
    __half* Ps = sh;                    // [128][PKS]: Q during setup, then P
    __half* Ks = sh + 128*PKS;          // [64][PKS]  K[k'][d]
    __half* Vs = sh + 192*PKS;          // [64][PKS]  V[k'][d]
    const unsigned short* Vh = (const unsigned short*)Vs;

    const int qi  = blockIdx.x, bh = blockIdx.y;
    const int tid = threadIdx.x, wid = tid >> 5, lane = tid & 31;
    const int g   = lane >> 2, t4 = lane & 3;
    const int r0  = wid*32;

    // stage Q (scaled by 0.125 = 2^-3, exact) into Ps as half
    const float* qg = Q + (size_t)(bh*S_ + qi*128) * DK_;
#pragma unroll
    for (int f = tid; f < 2048; f += 128) {
        const int r = f >> 4, c4 = (f & 15) << 2;
        float4 v = ((const float4*)qg)[f];
        *(uint2*)&Ps[r*PKS + c4] = make_uint2(
            pack_h2(v.x*0.125f, v.y*0.125f), pack_h2(v.z*0.125f, v.w*0.125f));
    }
    __syncthreads();

    // cache Q A-fragments for both 16-row halves: 2 x 4 ksteps x 4 regs
    uint32_t qa[2][4][4];
#pragma unroll
    for (int h = 0; h < 2; h++) {
        const int rb = r0 + h*16;
#pragma unroll
        for (int ks = 0; ks < 4; ++ks) {
            const int k0 = ks*16 + 2*t4;
            qa[h][ks][0] = *(const uint32_t*)&Ps[(rb + g    )*PKS + k0    ];
            qa[h][ks][1] = *(const uint32_t*)&Ps[(rb + 8 + g)*PKS + k0    ];
            qa[h][ks][2] = *(const uint32_t*)&Ps[(rb + g    )*PKS + k0 + 8];
            qa[h][ks][3] = *(const uint32_t*)&Ps[(rb + 8 + g)*PKS + k0 + 8];
        }
    }

    float co[2][8][4];
#pragma unroll
    for (int h = 0; h < 2; h++)
#pragma unroll
        for (int j = 0; j < 8; j++)
#pragma unroll
            for (int r = 0; r < 4; r++) co[h][j][r] = 0.f;
    float mrow[2][2] = {{-INFINITY,-INFINITY},{-INFINITY,-INFINITY}};
    float lrow[2][2] = {{0.f,0.f},{0.f,0.f}};

    const int kmax = 2*qi + 1;
    for (int kj = 0; kj <= kmax; ++kj) {
        __syncthreads();   // prev Ks/Vs consumed; iter0: all warps cached qa

        const float* kg = K + (size_t)(bh*S_ + kj*64) * DK_;
        const float* vg = V + (size_t)(bh*S_ + kj*64) * DK_;
#pragma unroll
        for (int f = tid; f < 1024; f += 128) {
            const int r = f >> 4, c4 = (f & 15) << 2;
            float4 kv = ((const float4*)kg)[f];
            *(uint2*)&Ks[r*PKS + c4] = make_uint2(
                pack_h2(kv.x, kv.y), pack_h2(kv.z, kv.w));
            float4 vv = ((const float4*)vg)[f];
            *(uint2*)&Vs[r*PKS + c4] = make_uint2(
                pack_h2(vv.x, vv.y), pack_h2(vv.z, vv.w));
        }
        __syncthreads();

        // ---- S = Q @ K^T, both halves share each B-frag
        float cs[2][8][4];
#pragma unroll
        for (int h = 0; h < 2; h++)
#pragma unroll
            for (int j = 0; j < 8; j++)
#pragma unroll
                for (int r = 0; r < 4; r++) cs[h][j][r] = 0.f;
#pragma unroll
        for (int ks = 0; ks < 4; ++ks) {
            const int k0 = ks*16 + 2*t4;
#pragma unroll
            for (int j = 0; j < 8; j++) {
                const uint32_t b0 = *(const uint32_t*)&Ks[(j*8 + g)*PKS + k0    ];
                const uint32_t b1 = *(const uint32_t*)&Ks[(j*8 + g)*PKS + k0 + 8];
                mma_f16(cs[0][j], qa[0][ks], b0, b1);
                mma_f16(cs[1][j], qa[1][ks], b0, b1);
            }
        }

        // ---- causal mask (only last two k-tiles clip)
        if (kj >= 2*qi) {
            const int dcol = (kj - 2*qi)*64;
#pragma unroll
            for (int h = 0; h < 2; h++)
#pragma unroll
                for (int j = 0; j < 8; j++)
#pragma unroll
                    for (int rr = 0; rr < 2; rr++)
#pragma unroll
                        for (int e = 0; e < 2; e++) {
                            const int row = r0 + h*16 + g + 8*rr;
                            const int col = dcol + j*8 + 2*t4 + e;
                            if (col > row) cs[h][j][2*rr + e] = -1e30f;
                        }
        }

        // ---- online softmax (quad reduction)
#pragma unroll
        for (int h = 0; h < 2; h++)
#pragma unroll
        for (int rr = 0; rr < 2; rr++) {
            float mt = -INFINITY;
#pragma unroll
            for (int j = 0; j < 8; j++)
                mt = fmaxf(mt, fmaxf(cs[h][j][2*rr], cs[h][j][2*rr + 1]));
            mt = fmaxf(mt, __shfl_xor_sync(0xffffffffu, mt, 1));
            mt = fmaxf(mt, __shfl_xor_sync(0xffffffffu, mt, 2));
            const float mn   = fmaxf(mrow[h][rr], mt);
            const float corr = __expf(mrow[h][rr] - mn);
            float ls = 0.f;
#pragma unroll
            for (int j = 0; j < 8; j++) {
                const float p0 = __expf(cs[h][j][2*rr    ] - mn);
                const float p1 = __expf(cs[h][j][2*rr + 1] - mn);
                cs[h][j][2*rr] = p0; cs[h][j][2*rr + 1] = p1;
                ls += p0 + p1;
            }
            ls += __shfl_xor_sync(0xffffffffu, ls, 1);
            ls += __shfl_xor_sync(0xffffffffu, ls, 2);
            lrow[h][rr] = lrow[h][rr]*corr + ls;
            mrow[h][rr] = mn;
#pragma unroll
            for (int j = 0; j < 8; j++) {
                co[h][j][2*rr] *= corr; co[h][j][2*rr + 1] *= corr;
            }
        }

        // ---- P -> Ps overlay (warp-local rows), half2 stores
#pragma unroll
        for (int h = 0; h < 2; h++)
#pragma unroll
        for (int rr = 0; rr < 2; rr++) {
            const int row = r0 + h*16 + g + 8*rr;
#pragma unroll
            for (int j = 0; j < 8; j++) {
                *(uint32_t*)&Ps[row*PKS + j*8 + 2*t4] =
                    pack_h2(cs[h][j][2*rr], cs[h][j][2*rr + 1]);
            }
        }
        __syncwarp();

        // ---- O += P @ V (V natural: b-frags from paired 16-bit LDS)
#pragma unroll
        for (int ks = 0; ks < 4; ++ks) {
            const int k0 = ks*16 + 2*t4;
            uint32_t a0[4], a1[4];
            a0[0] = *(const uint32_t*)&Ps[(r0 + g     )*PKS + k0    ];
            a0[1] = *(const uint32_t*)&Ps[(r0 + 8 + g )*PKS + k0    ];
            a0[2] = *(const uint32_t*)&Ps[(r0 + g     )*PKS + k0 + 8];
            a0[3] = *(const uint32_t*)&Ps[(r0 + 8 + g )*PKS + k0 + 8];
            a1[0] = *(const uint32_t*)&Ps[(r0 + 16 + g)*PKS + k0    ];
            a1[1] = *(const uint32_t*)&Ps[(r0 + 24 + g)*PKS + k0    ];
            a1[2] = *(const uint32_t*)&Ps[(r0 + 16 + g)*PKS + k0 + 8];
            a1[3] = *(const uint32_t*)&Ps[(r0 + 24 + g)*PKS + k0 + 8];
#pragma unroll
            for (int j = 0; j < 8; j++) {
                const int d = j*8 + g;
                const uint32_t b0 = (uint32_t)Vh[(k0    )*PKS + d]
                                  | ((uint32_t)Vh[(k0 + 1)*PKS + d] << 16);
                const uint32_t b1 = (uint32_t)Vh[(k0 + 8)*PKS + d]
                                  | ((uint32_t)Vh[(k0 + 9)*PKS + d] << 16);
                mma_f16(co[0][j], a0, b0, b1);
                mma_f16(co[1][j], a1, b0, b1);
            }
        }
    }

    // ---- finalize: /l, write to [B,S,D]
    const int bb = bh >> 4, h16 = bh & 15;
#pragma unroll
    for (int h = 0; h < 2; h++)
#pragma unroll
    for (int rr = 0; rr < 2; rr++) {
        const float inv = 1.0f / lrow[h][rr];
        const int srow = qi*128 + r0 + h*16 + g + 8*rr;
        float* og = O + ((size_t)(bb*S_ + srow))*D_ + h16*DK_;
#pragma unroll
        for (int j = 0; j < 8; j++) {
            *(float2*)&og[j*8 + 2*t4] = make_float2(
                co[h][j][2*rr]*inv, co[h][j][2*rr + 1]*inv);
        }
    }
}

// ---------------------------------------------------------------------------
extern "C" void kernel_launch(void* const* d_in, const int* in_sizes, int n_in,
                              void* d_out, int out_size)
{
    const float* q   = (const float*)d_in[0];
    const float* k   = (const float*)d_in[1];
    const float* v   = (const float*)d_in[2];
    const float* w_q = (const float*)d_in[4];
    const float* b_q = (const float*)d_in[5];
    const float* w_k = (const float*)d_in[6];
    const float* b_k = (const float*)d_in[7];
    const float* w_v = (const float*)d_in[8];
    const float* b_v = (const float*)d_in[9];
    const float* w_o = (const float*)d_in[10];
    const float* b_o = (const float*)d_in[11];
    float* out = (float*)d_out;

    float *Qp, *Kp, *Vp, *AOp;
    cudaGetSymbolAddress((void**)&Qp,  g_Q);
    cudaGetSymbolAddress((void**)&Kp,  g_K);
    cudaGetSymbolAddress((void**)&Vp,  g_V);
    cudaGetSymbolAddress((void**)&AOp, g_AO);

    cudaFuncSetAttribute(gemm_mma<1>, cudaFuncAttributeMaxDynamicSharedMemorySize, SMEM_GEMM);
    cudaFuncSetAttribute(gemm_mma<0>, cudaFuncAttributeMaxDynamicSharedMemorySize, SMEM_GEMM);
    cudaFuncSetAttribute(flash_mma,   cudaFuncAttributeMaxDynamicSharedMemorySize, FLASH_SMEM);

    dim3 ggrid(D_/128, M_/128);   // 8 x 64
    gemm_mma<1><<<ggrid, 256, SMEM_GEMM>>>(q, w_q, b_q, Qp);
    gemm_mma<1><<<ggrid, 256, SMEM_GEMM>>>(k, w_k, b_k, Kp);
    gemm_mma<1><<<ggrid, 256, SMEM_GEMM>>>(v, w_v, b_v, Vp);

    flash_mma<<<dim3(S_/128, B_*H_), 128, FLASH_SMEM>>>(Qp, Kp, Vp, AOp);

    gemm_mma<0><<<ggrid, 256, SMEM_GEMM>>>(AOp, w_o, b_o, out);
}